// round 3
// baseline (speedup 1.0000x reference)
#include <cuda_runtime.h>
#include <math.h>

// Problem constants
#define BQ 64              // queries per CTA tile
#define BN 64              // train rows per chunk
#define NSPLIT 28          // N-direction CTA splits
#define BTOT 2048          // number of queries
#define NTRAIN 50000
#define NPAD 50048         // padded to multiple of 64
#define NCHUNK (NPAD / BN) // 782
#define CDIM 16

// Scratch (device globals: allocation-free per harness rules)
__device__ float g_tsq[NPAD];
__device__ float g_xsq[BTOT];
__device__ float g_pp[NSPLIT * BTOT * CDIM];
__device__ float g_ws[NSPLIT * BTOT];

// ---------------------------------------------------------------------------
// Pass 0: squared norms. tsq padded with +inf so padded rows get weight 0.
// ---------------------------------------------------------------------------
__global__ void k_pre(const float* __restrict__ x, const float* __restrict__ trx) {
    int i = blockIdx.x * blockDim.x + threadIdx.x;
    if (i < NPAD) {
        float s = INFINITY;
        if (i < NTRAIN) {
            const float4* r = (const float4*)(trx + (size_t)i * 64);
            s = 0.f;
#pragma unroll
            for (int k = 0; k < 16; k++) {
                float4 v = r[k];
                s += v.x * v.x + v.y * v.y + v.z * v.z + v.w * v.w;
            }
        }
        g_tsq[i] = s;
    }
    if (i < BTOT) {
        const float4* r = (const float4*)(x + (size_t)i * 64);
        float s = 0.f;
#pragma unroll
        for (int k = 0; k < 16; k++) {
            float4 v = r[k];
            s += v.x * v.x + v.y * v.y + v.z * v.z + v.w * v.w;
        }
        g_xsq[i] = s;
    }
}

// ---------------------------------------------------------------------------
// Pass 1: fused cross-GEMM + exp + weighted-sum GEMM over an N slice.
//   CTA: 64 queries x (chunks j = blockIdx.y, step NSPLIT), 256 threads.
//   GEMM1: 4x4 micro-tile, float4 k-vector loads, XOR-swizzled smem.
//   GEMM2: thread = (q, c4), pred accumulates in 4 registers across chunks.
// ---------------------------------------------------------------------------
__global__ __launch_bounds__(256) void k_main(const float* __restrict__ x,
                                              const float* __restrict__ trx,
                                              const float* __restrict__ trY) {
    __shared__ float4 sA[BQ * 16];  // x tile   [m][kq ^ (m&15)]
    __shared__ float4 sB[BN * 16];  // t tile   [n][kq ^ (n&15)]   (aliased as W)
    __shared__ float4 sY[BN * 4];   // y tile   [n][c4]
    float* sWf = (float*)sB;        // W tile   [m*64 + (n ^ (m&15))]

    const int t = threadIdx.x;
    const int mbase = blockIdx.x * BQ;
    const int s = blockIdx.y;
    const int tx = t & 15, ty = t >> 4;

    // Load + swizzle x tile (once per CTA), coalesced float4
#pragma unroll
    for (int i = 0; i < 4; i++) {
        int e = t + i * 256;
        int kq = e & 15, m = e >> 4;
        sA[m * 16 + (kq ^ (m & 15))] =
            *(const float4*)(x + (size_t)(mbase + m) * 64 + kq * 4);
    }

    float xsq[4];
#pragma unroll
    for (int i = 0; i < 4; i++) xsq[i] = g_xsq[mbase + ty + 16 * i];

    float ws[4] = {0.f, 0.f, 0.f, 0.f};
    float4 pred = make_float4(0.f, 0.f, 0.f, 0.f);
    const int q = t >> 2, c4 = t & 3;
    const int qx = q & 15;

    for (int j = s; j < NCHUNK; j += NSPLIT) {
        const int nbase = j * BN;
        __syncthreads();  // prior GEMM2 done with sW(=sB)/sY before reload

        // Load train_x chunk (swizzled) and train_y chunk, zero-fill tail
#pragma unroll
        for (int i = 0; i < 4; i++) {
            int e = t + i * 256;
            int kq = e & 15, n = e >> 4;
            int gn = nbase + n;
            float4 v = make_float4(0.f, 0.f, 0.f, 0.f);
            if (gn < NTRAIN) v = *(const float4*)(trx + (size_t)gn * 64 + kq * 4);
            sB[n * 16 + (kq ^ (n & 15))] = v;
        }
        {
            int n = t >> 2, cc = t & 3;
            int gn = nbase + n;
            float4 v = make_float4(0.f, 0.f, 0.f, 0.f);
            if (gn < NTRAIN) v = *(const float4*)(trY + (size_t)gn * 16 + cc * 4);
            sY[n * 4 + cc] = v;
        }
        __syncthreads();

        // GEMM1: cross[m][n], m = ty+16i, n = tx+16j
        float c[4][4];
#pragma unroll
        for (int i = 0; i < 4; i++)
#pragma unroll
            for (int jj = 0; jj < 4; jj++) c[i][jj] = 0.f;

#pragma unroll
        for (int kq = 0; kq < 16; kq++) {
            float4 a[4], b[4];
#pragma unroll
            for (int i = 0; i < 4; i++)
                a[i] = sA[(ty + 16 * i) * 16 + (kq ^ ty)];
#pragma unroll
            for (int jj = 0; jj < 4; jj++)
                b[jj] = sB[(tx + 16 * jj) * 16 + (kq ^ tx)];
#pragma unroll
            for (int i = 0; i < 4; i++)
#pragma unroll
                for (int jj = 0; jj < 4; jj++) {
                    c[i][jj] += a[i].x * b[jj].x;
                    c[i][jj] += a[i].y * b[jj].y;
                    c[i][jj] += a[i].z * b[jj].z;
                    c[i][jj] += a[i].w * b[jj].w;
                }
        }
        __syncthreads();  // all threads done reading sB before overwrite as W

        // Fused epilogue: weights + row-sum + store W tile (swizzled)
#pragma unroll
        for (int jj = 0; jj < 4; jj++) {
            int n = tx + 16 * jj;
            float tsq = g_tsq[nbase + n];
#pragma unroll
            for (int i = 0; i < 4; i++) {
                float dn = 2.f * c[i][jj] - xsq[i] - tsq;  // = -distance
                float w = __expf(dn * 0.005f);             // exp(-d / (2*sigma^2))
                ws[i] += w;
                sWf[(ty + 16 * i) * 64 + (n ^ ty)] = w;
            }
        }
        __syncthreads();

        // GEMM2: pred[q][c4] += sum_n W[q][n] * Y[n][c4]
#pragma unroll 8
        for (int n = 0; n < 64; n++) {
            float w = sWf[q * 64 + (n ^ qx)];
            float4 y = sY[n * 4 + c4];
            pred.x += w * y.x;
            pred.y += w * y.y;
            pred.z += w * y.z;
            pred.w += w * y.w;
        }
    }

    // Write pred partials (unique (s, q, c4) per thread -> direct float4 store)
    *(float4*)(g_pp + ((size_t)(s * BTOT + mbase + q)) * CDIM + c4 * 4) = pred;

    // Reduce weight row-sums across the 16 tx lanes (lanes 0-15 / 16-31)
#pragma unroll
    for (int off = 8; off; off >>= 1)
#pragma unroll
        for (int i = 0; i < 4; i++)
            ws[i] += __shfl_down_sync(0xffffffffu, ws[i], off, 16);
    if (tx == 0) {
#pragma unroll
        for (int i = 0; i < 4; i++)
            g_ws[s * BTOT + mbase + ty + 16 * i] = ws[i];
    }
}

// ---------------------------------------------------------------------------
// Pass 2: reduce N-split partials, normalize.
// ---------------------------------------------------------------------------
__global__ void k_fin(float* __restrict__ out) {
    int i = blockIdx.x * blockDim.x + threadIdx.x;
    if (i >= BTOT * CDIM) return;
    int qd = i >> 4;
    float acc = 0.f, wsum = 0.f;
#pragma unroll
    for (int s = 0; s < NSPLIT; s++) {
        acc += g_pp[(size_t)s * BTOT * CDIM + i];
        wsum += g_ws[s * BTOT + qd];
    }
    out[i] = acc / (wsum + 1e-10f);
}

extern "C" void kernel_launch(void* const* d_in, const int* in_sizes, int n_in,
                              void* d_out, int out_size) {
    const float* x   = (const float*)d_in[0];
    const float* trx = (const float*)d_in[1];
    const float* trY = (const float*)d_in[2];
    float* out = (float*)d_out;

    k_pre<<<(NPAD + 255) / 256, 256>>>(x, trx);
    dim3 grid(BTOT / BQ, NSPLIT);
    k_main<<<grid, 256>>>(x, trx, trY);
    k_fin<<<(BTOT * CDIM + 255) / 256, 256>>>(out);
}

// round 6
// speedup vs baseline: 4.9184x; 4.9184x over previous
#include <cuda_runtime.h>
#include <cuda_bf16.h>
#include <math.h>
#include <stdint.h>

#define BTOT 2048
#define NTRAIN 50000
#define NPAD 50048
#define BN 128
#define NCH 391            // NPAD / BN
#define NSPLIT 9
#define CDIM 16
#define MT 128

// exp(-d/(2*sigma^2)) = 2^( c*K1 + (xsq+tsq)*K2 ),  c = dot(x,t); tsq/xsq pre-scaled by K2
#define K1f 0.014426950408889634f     //  0.01  * log2(e)
#define K2f (-0.0072134752044448170f) // -0.005 * log2(e)

// ---------------- device scratch ----------------
__device__ __align__(16) __nv_bfloat16 g_txb[(size_t)NPAD * 64];
__device__ __align__(16) __nv_bfloat16 g_xhi[(size_t)BTOT * 64];
__device__ __align__(16) __nv_bfloat16 g_xlo[(size_t)BTOT * 64];
__device__ __align__(16) __nv_bfloat16 g_tyhi[(size_t)CDIM * NPAD];
__device__ __align__(16) __nv_bfloat16 g_tylo[(size_t)CDIM * NPAD];
__device__ float g_tsq[NPAD];   // pre-scaled by K2f (+pad rows = -inf)
__device__ float g_xsq[BTOT];   // pre-scaled by K2f
__device__ float g_pp[NSPLIT * BTOT * CDIM];
__device__ float g_ws[NSPLIT * BTOT];

// ---------------- helpers ----------------
static __device__ __forceinline__ uint32_t s2u(const void* p) {
    uint32_t a;
    asm("{ .reg .u64 t; cvta.to.shared.u64 t, %1; cvt.u32.u64 %0, t; }" : "=r"(a) : "l"(p));
    return a;
}
static __device__ __forceinline__ float ex2f(float x) {
    float r; asm("ex2.approx.ftz.f32 %0, %1;" : "=f"(r) : "f"(x)); return r;
}
static __device__ __forceinline__ void cpa16(uint32_t dst, const void* src) {
    asm volatile("cp.async.cg.shared.global [%0], [%1], 16;" :: "r"(dst), "l"(src));
}
static __device__ __forceinline__ void cpa4(uint32_t dst, const void* src) {
    asm volatile("cp.async.ca.shared.global [%0], [%1], 4;" :: "r"(dst), "l"(src));
}
static __device__ __forceinline__ void cpcommit() { asm volatile("cp.async.commit_group;"); }
static __device__ __forceinline__ void cpwait0() { asm volatile("cp.async.wait_group 0;"); }

static __device__ __forceinline__ void ldsm4(uint32_t* r, uint32_t addr) {
    asm volatile("ldmatrix.sync.aligned.m8n8.x4.shared.b16 {%0,%1,%2,%3}, [%4];"
                 : "=r"(r[0]), "=r"(r[1]), "=r"(r[2]), "=r"(r[3]) : "r"(addr));
}
static __device__ __forceinline__ void mma16816(float* d, const uint32_t* a,
                                                uint32_t b0, uint32_t b1) {
    asm volatile(
        "mma.sync.aligned.m16n8k16.row.col.f32.bf16.bf16.f32 "
        "{%0,%1,%2,%3}, {%4,%5,%6,%7}, {%8,%9}, {%0,%1,%2,%3};"
        : "+f"(d[0]), "+f"(d[1]), "+f"(d[2]), "+f"(d[3])
        : "r"(a[0]), "r"(a[1]), "r"(a[2]), "r"(a[3]), "r"(b0), "r"(b1));
}
static __device__ __forceinline__ uint32_t pack_bf(float hi, float lo) {
    uint32_t r; asm("cvt.rn.bf16x2.f32 %0, %1, %2;" : "=r"(r) : "f"(hi), "f"(lo));
    return r;
}

#define SW(o) ((uint32_t)(o) ^ ((((uint32_t)(o)) >> 3) & 0x70u))

// smem layout (bytes)
#define OFF_TSQ 0       // 2 x 512
#define OFF_X   1024    // hi 16K, lo 16K
#define OFF_T   33792   // 2 x 16K
#define OFF_Y   66560   // 2 x (hi 4K + lo 4K)
#define SMEM_SZ 82944

// =====================================================================
// Precompute kernels
// =====================================================================
__global__ void k_cvtx(const float* __restrict__ trx) {
    size_t gid = (size_t)blockIdx.x * blockDim.x + threadIdx.x;
    if (gid >= (size_t)NPAD * 16) return;
    size_t e = gid * 4;
    int row = (int)(e >> 6);
    float4 v = make_float4(0.f, 0.f, 0.f, 0.f);
    if (row < NTRAIN) v = *(const float4*)(trx + e);
    *(__nv_bfloat162*)(g_txb + e) = __floats2bfloat162_rn(v.x, v.y);
    *(__nv_bfloat162*)(g_txb + e + 2) = __floats2bfloat162_rn(v.z, v.w);
}

__global__ void k_ty(const float* __restrict__ trY) {
    __shared__ __nv_bfloat16 shi[16][256];
    __shared__ __nv_bfloat16 slo[16][256];
    int n0 = blockIdx.x * 256;
    int t = threadIdx.x;
#pragma unroll
    for (int it = 0; it < 16; it++) {
        int e = t + it * 256;
        int r = e >> 4, c = e & 15;
        int row = n0 + r;
        float v = (row < NTRAIN) ? trY[(size_t)row * 16 + c] : 0.f;
        __nv_bfloat16 h = __float2bfloat16(v);
        shi[c][r] = h;
        slo[c][r] = __float2bfloat16(v - __bfloat162float(h));
    }
    __syncthreads();
    if (n0 + t < NPAD) {
#pragma unroll
        for (int c = 0; c < 16; c++) {
            g_tyhi[(size_t)c * NPAD + n0 + t] = shi[c][t];
            g_tylo[(size_t)c * NPAD + n0 + t] = slo[c][t];
        }
    }
}

__global__ void k_norm(const float* __restrict__ x, const float* __restrict__ trx) {
    int i = blockIdx.x * blockDim.x + threadIdx.x;
    if (i < NPAD) {
        float s = -INFINITY;  // pad rows -> weight 0
        if (i < NTRAIN) {
            const float4* r = (const float4*)(trx + (size_t)i * 64);
            float a = 0.f;
#pragma unroll
            for (int k = 0; k < 16; k++) {
                float4 v = r[k];
                a += v.x * v.x + v.y * v.y + v.z * v.z + v.w * v.w;
            }
            s = a * K2f;
        }
        g_tsq[i] = s;
    }
    if (i < BTOT) {
        const float4* r = (const float4*)(x + (size_t)i * 64);
        float s = 0.f;
#pragma unroll
        for (int k = 0; k < 16; k++) {
            float4 v = r[k];
            s += v.x * v.x + v.y * v.y + v.z * v.z + v.w * v.w;
            float vv[4] = {v.x, v.y, v.z, v.w};
#pragma unroll
            for (int q = 0; q < 4; q++) {
                __nv_bfloat16 h = __float2bfloat16(vv[q]);
                g_xhi[(size_t)i * 64 + k * 4 + q] = h;
                g_xlo[(size_t)i * 64 + k * 4 + q] =
                    __float2bfloat16(vv[q] - __bfloat162float(h));
            }
        }
        g_xsq[i] = s * K2f;
    }
}

// =====================================================================
// Main fused kernel: mma.sync GEMM1 -> register exp epilogue -> mma.sync GEMM2
// =====================================================================
__global__ void __launch_bounds__(256, 1) k_main() {
    extern __shared__ char smem[];
    const uint32_t sb = s2u(smem);
    const int t = threadIdx.x;
    const int wid = t >> 5, lane = t & 31;
    const int mbase = blockIdx.x * MT;
    const int s = blockIdx.y;

    // ldmatrix lane mapping
    const int l8 = lane & 7, lq = lane >> 3;
    const int lr = l8 + ((lq & 1) << 3);  // row within 16
    const int lh = lq >> 1;               // 16B column half

    // ---- prologue loads: x tiles (hi/lo) + chunk0 ----
#pragma unroll
    for (int i = 0; i < 8; i++) {
        int e = t + i * 256;
        int half = e >> 10, r = e & 1023;
        int row = r >> 3, u = r & 7;
        const __nv_bfloat16* src =
            (half ? g_xlo : g_xhi) + (size_t)(mbase + row) * 64 + u * 8;
        cpa16(sb + OFF_X + half * 16384 + SW(row * 128 + u * 16), src);
    }
    auto load_chunk = [&](int ch, int b) {
        int nb = ch * BN;
#pragma unroll
        for (int i = 0; i < 4; i++) {
            int e = t + i * 256;
            int row = e >> 3, u = e & 7;
            cpa16(sb + OFF_T + b * 16384 + SW(row * 128 + u * 16),
                  g_txb + (size_t)(nb + row) * 64 + u * 8);
        }
#pragma unroll
        for (int i = 0; i < 2; i++) {
            int e = t + i * 256;
            int half = e >> 8, r = e & 255;
            int nblk = r >> 4, c = r & 15;
            const __nv_bfloat16* src =
                (half ? g_tylo : g_tyhi) + (size_t)c * NPAD + nb + nblk * 8;
            cpa16(sb + OFF_Y + b * 8192 + half * 4096 + c * 256 +
                      (((uint32_t)(nblk ^ c)) << 4),
                  src);
        }
        if (t < 128) cpa4(sb + OFF_TSQ + b * 512 + t * 4, g_tsq + nb + t);
    };
    load_chunk(s, 0);
    cpcommit();
    cpwait0();
    __syncthreads();

    // ---- hoist A fragments (x hi/lo) into registers ----
    uint32_t axh[4][4], axl[4][4];
#pragma unroll
    for (int kt = 0; kt < 4; kt++) {
        uint32_t o = SW((wid * 16 + lr) * 128 + kt * 32 + lh * 16);
        ldsm4(axh[kt], sb + OFF_X + o);
        ldsm4(axl[kt], sb + OFF_X + 16384 + o);
    }
    const int r0 = wid * 16 + (lane >> 2);
    const float xsk0 = g_xsq[mbase + r0];
    const float xsk1 = g_xsq[mbase + r0 + 8];

    float acc0[4] = {0.f, 0.f, 0.f, 0.f};  // pred channels 0-7
    float acc1[4] = {0.f, 0.f, 0.f, 0.f};  // pred channels 8-15
    float ws0 = 0.f, ws1 = 0.f;

    for (int ch = s, jj = 0; ch < NCH; ch += NSPLIT, jj++) {
        const int b = jj & 1;
        if (ch + NSPLIT < NCH) load_chunk(ch + NSPLIT, b ^ 1);
        cpcommit();

        // ---- GEMM1: c[16 ntiles][4] = (xhi+xlo) . trx^T ----
        float c[16][4];
#pragma unroll
        for (int j = 0; j < 16; j++)
#pragma unroll
            for (int q = 0; q < 4; q++) c[j][q] = 0.f;

        const uint32_t tb = sb + OFF_T + b * 16384;
#pragma unroll
        for (int np = 0; np < 8; np++) {
#pragma unroll
            for (int kt = 0; kt < 4; kt++) {
                uint32_t bt[4];
                ldsm4(bt, tb + SW((np * 16 + lr) * 128 + kt * 32 + lh * 16));
                mma16816(c[2 * np], axh[kt], bt[0], bt[2]);
                mma16816(c[2 * np], axl[kt], bt[0], bt[2]);
                mma16816(c[2 * np + 1], axh[kt], bt[1], bt[3]);
                mma16816(c[2 * np + 1], axl[kt], bt[1], bt[3]);
            }
        }

        // ---- fused epilogue + GEMM2, per k-tile of the n dimension ----
        const uint32_t tsb = sb + OFF_TSQ + b * 512;
        const uint32_t yb = sb + OFF_Y + b * 8192;
        const int cc2 = 2 * (lane & 3);
#pragma unroll
        for (int kt = 0; kt < 8; kt++) {
            uint32_t ah[4], al[4];
#pragma unroll
            for (int jn = 0; jn < 2; jn++) {
                const int j = 2 * kt + jn;
                float2 tq = *(float2*)(smem + (tsb - sb) + (j * 8 + cc2) * 4);
                float w0 = ex2f(fmaf(c[j][0], K1f, xsk0 + tq.x));
                float w1 = ex2f(fmaf(c[j][1], K1f, xsk0 + tq.y));
                float w2 = ex2f(fmaf(c[j][2], K1f, xsk1 + tq.x));
                float w3 = ex2f(fmaf(c[j][3], K1f, xsk1 + tq.y));
                ws0 += w0 + w1;
                ws1 += w2 + w3;
                uint32_t h01 = pack_bf(w1, w0);
                uint32_t h23 = pack_bf(w3, w2);
                float f0 = __uint_as_float(h01 << 16);
                float f1 = __uint_as_float(h01 & 0xffff0000u);
                float f2 = __uint_as_float(h23 << 16);
                float f3 = __uint_as_float(h23 & 0xffff0000u);
                ah[jn * 2 + 0] = h01;
                ah[jn * 2 + 1] = h23;
                al[jn * 2 + 0] = pack_bf(w1 - f1, w0 - f0);
                al[jn * 2 + 1] = pack_bf(w3 - f3, w2 - f2);
            }
            // A-frag order: {j0 rows r, j0 rows r+8, j1 rows r, j1 rows r+8} = {ah0,ah1,ah2,ah3}
            uint32_t bh[4], bl[4];
            {
                uint32_t col = (uint32_t)((2 * kt + lh) ^ lr) << 4;
                ldsm4(bh, yb + lr * 256 + col);
                ldsm4(bl, yb + 4096 + lr * 256 + col);
            }
            mma16816(acc0, ah, bh[0], bh[2]);
            mma16816(acc1, ah, bh[1], bh[3]);
            mma16816(acc0, al, bh[0], bh[2]);
            mma16816(acc1, al, bh[1], bh[3]);
            mma16816(acc0, ah, bl[0], bl[2]);
            mma16816(acc1, ah, bl[1], bl[3]);
        }

        cpwait0();
        __syncthreads();
    }

    // ---- store pred partials ----
    {
        float* p0 = g_pp + ((size_t)s * BTOT + mbase + r0) * CDIM;
        float* p1 = p0 + 8 * CDIM;
        const int cc = 2 * (lane & 3);
        *(float2*)(p0 + cc) = make_float2(acc0[0], acc0[1]);
        *(float2*)(p0 + 8 + cc) = make_float2(acc1[0], acc1[1]);
        *(float2*)(p1 + cc) = make_float2(acc0[2], acc0[3]);
        *(float2*)(p1 + 8 + cc) = make_float2(acc1[2], acc1[3]);
    }
    // ---- reduce row-sums across the 4 lanes sharing a row ----
#pragma unroll
    for (int off = 1; off <= 2; off <<= 1) {
        ws0 += __shfl_xor_sync(0xffffffffu, ws0, off);
        ws1 += __shfl_xor_sync(0xffffffffu, ws1, off);
    }
    if ((lane & 3) == 0) {
        g_ws[s * BTOT + mbase + r0] = ws0;
        g_ws[s * BTOT + mbase + r0 + 8] = ws1;
    }
}

// =====================================================================
// Reduce N-split partials + normalize
// =====================================================================
__global__ void k_fin(float* __restrict__ out) {
    int i = blockIdx.x * blockDim.x + threadIdx.x;
    if (i >= BTOT * CDIM) return;
    int qd = i >> 4;
    float acc = 0.f, wsum = 0.f;
#pragma unroll
    for (int s = 0; s < NSPLIT; s++) {
        acc += g_pp[(size_t)s * BTOT * CDIM + i];
        wsum += g_ws[s * BTOT + qd];
    }
    out[i] = acc / (wsum + 1e-10f);
}

extern "C" void kernel_launch(void* const* d_in, const int* in_sizes, int n_in,
                              void* d_out, int out_size) {
    const float* x   = (const float*)d_in[0];
    const float* trx = (const float*)d_in[1];
    const float* trY = (const float*)d_in[2];
    float* out = (float*)d_out;

    cudaFuncSetAttribute(k_main, cudaFuncAttributeMaxDynamicSharedMemorySize, SMEM_SZ);

    k_cvtx<<<(NPAD * 16 + 255) / 256, 256>>>(trx);
    k_ty<<<(NPAD + 255) / 256, 256>>>(trY);
    k_norm<<<(NPAD + 255) / 256, 256>>>(x, trx);
    dim3 grid(BTOT / MT, NSPLIT);
    k_main<<<grid, 256, SMEM_SZ>>>();
    k_fin<<<(BTOT * CDIM + 255) / 256, 256>>>(out);
}

// round 8
// speedup vs baseline: 6.9894x; 1.4211x over previous
#include <cuda_runtime.h>
#include <cuda_fp16.h>
#include <math.h>
#include <stdint.h>

#define BTOT 2048
#define NTRAIN 50000
#define NPAD 50048
#define BN 128
#define NCH 391            // NPAD / BN
#define NSPLIT 9
#define CDIM 16
#define MT 128

// exp(-d/(2*sigma^2)) = 2^( c*K1 + (xsq+tsq)*K2 ),  c = dot(x,t); tsq/xsq pre-scaled by K2
#define K1f 0.014426950408889634f     //  0.01  * log2(e)
#define K2f (-0.0072134752044448170f) // -0.005 * log2(e)

// ---------------- device scratch ----------------
__device__ __align__(16) __half g_txb[(size_t)NPAD * 64];
__device__ __align__(16) __half g_xh[(size_t)BTOT * 64];
__device__ __align__(16) __half g_tyhi[(size_t)CDIM * NPAD];
__device__ __align__(16) __half g_tylo[(size_t)CDIM * NPAD];
__device__ float g_tsq[NPAD];   // pre-scaled by K2f (+pad rows = -inf)
__device__ float g_xsq[BTOT];   // pre-scaled by K2f
__device__ float g_pp[NSPLIT * BTOT * CDIM];
__device__ float g_ws[NSPLIT * BTOT];

// ---------------- helpers ----------------
static __device__ __forceinline__ uint32_t s2u(const void* p) {
    uint32_t a;
    asm("{ .reg .u64 t; cvta.to.shared.u64 t, %1; cvt.u32.u64 %0, t; }" : "=r"(a) : "l"(p));
    return a;
}
static __device__ __forceinline__ float ex2f(float x) {
    float r; asm("ex2.approx.ftz.f32 %0, %1;" : "=f"(r) : "f"(x)); return r;
}
static __device__ __forceinline__ void cpa16(uint32_t dst, const void* src) {
    asm volatile("cp.async.cg.shared.global [%0], [%1], 16;" :: "r"(dst), "l"(src));
}
static __device__ __forceinline__ void cpa4(uint32_t dst, const void* src) {
    asm volatile("cp.async.ca.shared.global [%0], [%1], 4;" :: "r"(dst), "l"(src));
}
static __device__ __forceinline__ void cpcommit() { asm volatile("cp.async.commit_group;"); }
static __device__ __forceinline__ void cpwait0() { asm volatile("cp.async.wait_group 0;"); }

static __device__ __forceinline__ void ldsm4(uint32_t* r, uint32_t addr) {
    asm volatile("ldmatrix.sync.aligned.m8n8.x4.shared.b16 {%0,%1,%2,%3}, [%4];"
                 : "=r"(r[0]), "=r"(r[1]), "=r"(r[2]), "=r"(r[3]) : "r"(addr));
}
static __device__ __forceinline__ void mma16816(float* d, const uint32_t* a,
                                                uint32_t b0, uint32_t b1) {
    asm volatile(
        "mma.sync.aligned.m16n8k16.row.col.f32.f16.f16.f32 "
        "{%0,%1,%2,%3}, {%4,%5,%6,%7}, {%8,%9}, {%0,%1,%2,%3};"
        : "+f"(d[0]), "+f"(d[1]), "+f"(d[2]), "+f"(d[3])
        : "r"(a[0]), "r"(a[1]), "r"(a[2]), "r"(a[3]), "r"(b0), "r"(b1));
}
static __device__ __forceinline__ uint32_t pack_hf(float hi, float lo) {
    uint32_t r; asm("cvt.rn.f16x2.f32 %0, %1, %2;" : "=r"(r) : "f"(hi), "f"(lo));
    return r;
}

#define SW(o) ((uint32_t)(o) ^ ((((uint32_t)(o)) >> 3) & 0x70u))

// smem layout (bytes)
#define OFF_TSQ 0       // 2 x 512
#define OFF_X   1024    // 16K (fp16 x tile)
#define OFF_T   17408   // 2 x 16K
#define OFF_Y   50176   // 2 x (hi 4K + lo 4K)
#define SMEM_SZ 66560

// =====================================================================
// Precompute kernels
// =====================================================================
__global__ void k_cvtx(const float* __restrict__ trx) {
    size_t gid = (size_t)blockIdx.x * blockDim.x + threadIdx.x;
    if (gid >= (size_t)NPAD * 16) return;
    size_t e = gid * 4;
    int row = (int)(e >> 6);
    float4 v = make_float4(0.f, 0.f, 0.f, 0.f);
    if (row < NTRAIN) v = *(const float4*)(trx + e);
    *(__half2*)(g_txb + e) = __floats2half2_rn(v.x, v.y);
    *(__half2*)(g_txb + e + 2) = __floats2half2_rn(v.z, v.w);
}

__global__ void k_ty(const float* __restrict__ trY) {
    __shared__ __half shi[16][256];
    __shared__ __half slo[16][256];
    int n0 = blockIdx.x * 256;
    int t = threadIdx.x;
#pragma unroll
    for (int it = 0; it < 16; it++) {
        int e = t + it * 256;
        int r = e >> 4, c = e & 15;
        int row = n0 + r;
        float v = (row < NTRAIN) ? trY[(size_t)row * 16 + c] : 0.f;
        __half h = __float2half_rn(v);
        shi[c][r] = h;
        slo[c][r] = __float2half_rn(v - __half2float(h));
    }
    __syncthreads();
    if (n0 + t < NPAD) {
#pragma unroll
        for (int c = 0; c < 16; c++) {
            g_tyhi[(size_t)c * NPAD + n0 + t] = shi[c][t];
            g_tylo[(size_t)c * NPAD + n0 + t] = slo[c][t];
        }
    }
}

__global__ void k_norm(const float* __restrict__ x, const float* __restrict__ trx) {
    int i = blockIdx.x * blockDim.x + threadIdx.x;
    if (i < NPAD) {
        float s = -INFINITY;  // pad rows -> weight 0
        if (i < NTRAIN) {
            const float4* r = (const float4*)(trx + (size_t)i * 64);
            float a = 0.f;
#pragma unroll
            for (int k = 0; k < 16; k++) {
                float4 v = r[k];
                a += v.x * v.x + v.y * v.y + v.z * v.z + v.w * v.w;
            }
            s = a * K2f;
        }
        g_tsq[i] = s;
    }
    if (i < BTOT) {
        const float4* r = (const float4*)(x + (size_t)i * 64);
        float s = 0.f;
#pragma unroll
        for (int k = 0; k < 16; k++) {
            float4 v = r[k];
            s += v.x * v.x + v.y * v.y + v.z * v.z + v.w * v.w;
            *(__half2*)(g_xh + (size_t)i * 64 + k * 4) = __floats2half2_rn(v.x, v.y);
            *(__half2*)(g_xh + (size_t)i * 64 + k * 4 + 2) = __floats2half2_rn(v.z, v.w);
        }
        g_xsq[i] = s * K2f;
    }
}

// =====================================================================
// Main fused kernel: fp16 mma GEMM1 -> register exp epilogue -> fp16 mma GEMM2
// =====================================================================
__global__ void __launch_bounds__(256, 1) k_main() {
    extern __shared__ char smem[];
    const uint32_t sb = s2u(smem);
    const int t = threadIdx.x;
    const int wid = t >> 5, lane = t & 31;
    const int mbase = blockIdx.x * MT;
    const int s = blockIdx.y;

    // ldmatrix lane mapping
    const int l8 = lane & 7, lq = lane >> 3;
    const int lr = l8 + ((lq & 1) << 3);  // row within 16
    const int lh = lq >> 1;               // 16B column half

    // ---- prologue loads: x tile + chunk0 ----
#pragma unroll
    for (int i = 0; i < 4; i++) {
        int e = t + i * 256;
        int row = e >> 3, u = e & 7;
        cpa16(sb + OFF_X + SW(row * 128 + u * 16),
              g_xh + (size_t)(mbase + row) * 64 + u * 8);
    }
    auto load_chunk = [&](int ch, int b) {
        int nb = ch * BN;
#pragma unroll
        for (int i = 0; i < 4; i++) {
            int e = t + i * 256;
            int row = e >> 3, u = e & 7;
            cpa16(sb + OFF_T + b * 16384 + SW(row * 128 + u * 16),
                  g_txb + (size_t)(nb + row) * 64 + u * 8);
        }
#pragma unroll
        for (int i = 0; i < 2; i++) {
            int e = t + i * 256;
            int half = e >> 8, r = e & 255;
            int nblk = r >> 4, c = r & 15;
            const __half* src =
                (half ? g_tylo : g_tyhi) + (size_t)c * NPAD + nb + nblk * 8;
            cpa16(sb + OFF_Y + b * 8192 + half * 4096 + c * 256 +
                      (((uint32_t)(nblk ^ c)) << 4),
                  src);
        }
        if (t < 128) cpa4(sb + OFF_TSQ + b * 512 + t * 4, g_tsq + nb + t);
    };
    load_chunk(s, 0);
    cpcommit();
    cpwait0();
    __syncthreads();

    // ---- hoist A fragments (x fp16) into registers ----
    uint32_t ax[4][4];
#pragma unroll
    for (int kt = 0; kt < 4; kt++) {
        uint32_t o = SW((wid * 16 + lr) * 128 + kt * 32 + lh * 16);
        ldsm4(ax[kt], sb + OFF_X + o);
    }
    const int r0 = wid * 16 + (lane >> 2);
    const float xsk0 = g_xsq[mbase + r0];
    const float xsk1 = g_xsq[mbase + r0 + 8];

    float acc0[4] = {0.f, 0.f, 0.f, 0.f};  // pred channels 0-7
    float acc1[4] = {0.f, 0.f, 0.f, 0.f};  // pred channels 8-15
    float ws0 = 0.f, ws1 = 0.f;

    for (int ch = s, jj = 0; ch < NCH; ch += NSPLIT, jj++) {
        const int b = jj & 1;
        if (ch + NSPLIT < NCH) load_chunk(ch + NSPLIT, b ^ 1);
        cpcommit();

        // ---- GEMM1: c[16 ntiles][4] = x . trx^T (fp16 single) ----
        float c[16][4];
#pragma unroll
        for (int j = 0; j < 16; j++)
#pragma unroll
            for (int q = 0; q < 4; q++) c[j][q] = 0.f;

        const uint32_t tb = sb + OFF_T + b * 16384;
#pragma unroll
        for (int np = 0; np < 8; np++) {
#pragma unroll
            for (int kt = 0; kt < 4; kt++) {
                uint32_t bt[4];
                ldsm4(bt, tb + SW((np * 16 + lr) * 128 + kt * 32 + lh * 16));
                mma16816(c[2 * np], ax[kt], bt[0], bt[2]);
                mma16816(c[2 * np + 1], ax[kt], bt[1], bt[3]);
            }
        }

        // ---- fused epilogue + GEMM2, per k-tile of the n dimension ----
        const uint32_t tsb = sb + OFF_TSQ + b * 512;
        const uint32_t yb = sb + OFF_Y + b * 8192;
        const int cc2 = 2 * (lane & 3);
#pragma unroll
        for (int kt = 0; kt < 8; kt++) {
            uint32_t ah[4];
#pragma unroll
            for (int jn = 0; jn < 2; jn++) {
                const int j = 2 * kt + jn;
                float2 tq = *(float2*)(smem + (tsb - sb) + (j * 8 + cc2) * 4);
                float w0 = ex2f(fmaf(c[j][0], K1f, xsk0 + tq.x));
                float w1 = ex2f(fmaf(c[j][1], K1f, xsk0 + tq.y));
                float w2 = ex2f(fmaf(c[j][2], K1f, xsk1 + tq.x));
                float w3 = ex2f(fmaf(c[j][3], K1f, xsk1 + tq.y));
                ws0 += w0 + w1;
                ws1 += w2 + w3;
                ah[jn * 2 + 0] = pack_hf(w1, w0);
                ah[jn * 2 + 1] = pack_hf(w3, w2);
            }
            // A-frag order: {j0 rows r, j0 rows r+8, j1 rows r, j1 rows r+8}
            uint32_t bh[4], bl[4];
            {
                uint32_t col = (uint32_t)((2 * kt + lh) ^ lr) << 4;
                ldsm4(bh, yb + lr * 256 + col);
                ldsm4(bl, yb + 4096 + lr * 256 + col);
            }
            mma16816(acc0, ah, bh[0], bh[2]);
            mma16816(acc1, ah, bh[1], bh[3]);
            mma16816(acc0, ah, bl[0], bl[2]);
            mma16816(acc1, ah, bl[1], bl[3]);
        }

        cpwait0();
        __syncthreads();
    }

    // ---- store pred partials ----
    {
        float* p0 = g_pp + ((size_t)s * BTOT + mbase + r0) * CDIM;
        float* p1 = p0 + 8 * CDIM;
        const int cc = 2 * (lane & 3);
        *(float2*)(p0 + cc) = make_float2(acc0[0], acc0[1]);
        *(float2*)(p0 + 8 + cc) = make_float2(acc1[0], acc1[1]);
        *(float2*)(p1 + cc) = make_float2(acc0[2], acc0[3]);
        *(float2*)(p1 + 8 + cc) = make_float2(acc1[2], acc1[3]);
    }
    // ---- reduce row-sums across the 4 lanes sharing a row ----
#pragma unroll
    for (int off = 1; off <= 2; off <<= 1) {
        ws0 += __shfl_xor_sync(0xffffffffu, ws0, off);
        ws1 += __shfl_xor_sync(0xffffffffu, ws1, off);
    }
    if ((lane & 3) == 0) {
        g_ws[s * BTOT + mbase + r0] = ws0;
        g_ws[s * BTOT + mbase + r0 + 8] = ws1;
    }
}

// =====================================================================
// Reduce N-split partials + normalize
// =====================================================================
__global__ void k_fin(float* __restrict__ out) {
    int i = blockIdx.x * blockDim.x + threadIdx.x;
    if (i >= BTOT * CDIM) return;
    int qd = i >> 4;
    float acc = 0.f, wsum = 0.f;
#pragma unroll
    for (int s = 0; s < NSPLIT; s++) {
        acc += g_pp[(size_t)s * BTOT * CDIM + i];
        wsum += g_ws[s * BTOT + qd];
    }
    out[i] = acc / (wsum + 1e-10f);
}

extern "C" void kernel_launch(void* const* d_in, const int* in_sizes, int n_in,
                              void* d_out, int out_size) {
    const float* x   = (const float*)d_in[0];
    const float* trx = (const float*)d_in[1];
    const float* trY = (const float*)d_in[2];
    float* out = (float*)d_out;

    cudaFuncSetAttribute(k_main, cudaFuncAttributeMaxDynamicSharedMemorySize, SMEM_SZ);

    k_cvtx<<<(NPAD * 16 + 255) / 256, 256>>>(trx);
    k_ty<<<(NPAD + 255) / 256, 256>>>(trY);
    k_norm<<<(NPAD + 255) / 256, 256>>>(x, trx);
    dim3 grid(BTOT / MT, NSPLIT);
    k_main<<<grid, 256, SMEM_SZ>>>();
    k_fin<<<(BTOT * CDIM + 255) / 256, 256>>>(out);
}

// round 9
// speedup vs baseline: 7.5922x; 1.0862x over previous
#include <cuda_runtime.h>
#include <cuda_fp16.h>
#include <math.h>
#include <stdint.h>

#define BTOT 2048
#define NTRAIN 50000
#define NPAD 50048
#define BN 128
#define NCH 391            // NPAD / BN
#define NSPLIT 18
#define CDIM 16
#define MT 128

// exp(-d/(2*sigma^2)) = 2^( c*K1 + (xsq+tsq)*K2 ),  c = dot(x,t); tsq/xsq pre-scaled by K2
#define K1f 0.014426950408889634f     //  0.01  * log2(e)
#define K2f (-0.0072134752044448170f) // -0.005 * log2(e)

// ---------------- device scratch ----------------
__device__ __align__(16) __half g_txb[(size_t)NPAD * 64];
__device__ __align__(16) __half g_xh[(size_t)BTOT * 64];
__device__ __align__(16) __half g_tyhi[(size_t)CDIM * NPAD];
__device__ __align__(16) __half g_tylo[(size_t)CDIM * NPAD];
__device__ float g_tsq[NPAD];   // pre-scaled by K2f (+pad rows = -inf)
__device__ float g_xsq[BTOT];   // pre-scaled by K2f
__device__ float g_pp[NSPLIT * BTOT * CDIM];
__device__ float g_ws[NSPLIT * BTOT];

// ---------------- helpers ----------------
static __device__ __forceinline__ uint32_t s2u(const void* p) {
    uint32_t a;
    asm("{ .reg .u64 t; cvta.to.shared.u64 t, %1; cvt.u32.u64 %0, t; }" : "=r"(a) : "l"(p));
    return a;
}
static __device__ __forceinline__ float ex2f(float x) {
    float r; asm("ex2.approx.ftz.f32 %0, %1;" : "=f"(r) : "f"(x)); return r;
}
static __device__ __forceinline__ void cpa16(uint32_t dst, const void* src) {
    asm volatile("cp.async.cg.shared.global [%0], [%1], 16;" :: "r"(dst), "l"(src));
}
static __device__ __forceinline__ void cpa4(uint32_t dst, const void* src) {
    asm volatile("cp.async.ca.shared.global [%0], [%1], 4;" :: "r"(dst), "l"(src));
}
static __device__ __forceinline__ void cpcommit() { asm volatile("cp.async.commit_group;"); }
static __device__ __forceinline__ void cpwait0() { asm volatile("cp.async.wait_group 0;"); }

static __device__ __forceinline__ void ldsm4(uint32_t* r, uint32_t addr) {
    asm volatile("ldmatrix.sync.aligned.m8n8.x4.shared.b16 {%0,%1,%2,%3}, [%4];"
                 : "=r"(r[0]), "=r"(r[1]), "=r"(r[2]), "=r"(r[3]) : "r"(addr));
}
static __device__ __forceinline__ void mma16816(float* d, const uint32_t* a,
                                                uint32_t b0, uint32_t b1) {
    asm volatile(
        "mma.sync.aligned.m16n8k16.row.col.f32.f16.f16.f32 "
        "{%0,%1,%2,%3}, {%4,%5,%6,%7}, {%8,%9}, {%0,%1,%2,%3};"
        : "+f"(d[0]), "+f"(d[1]), "+f"(d[2]), "+f"(d[3])
        : "r"(a[0]), "r"(a[1]), "r"(a[2]), "r"(a[3]), "r"(b0), "r"(b1));
}
static __device__ __forceinline__ uint32_t pack_hf(float hi, float lo) {
    uint32_t r; asm("cvt.rn.f16x2.f32 %0, %1, %2;" : "=r"(r) : "f"(hi), "f"(lo));
    return r;
}

#define SW(o) ((uint32_t)(o) ^ ((((uint32_t)(o)) >> 3) & 0x70u))

// smem layout (bytes)
#define OFF_TSQ 0       // 2 x 512
#define OFF_X   1024    // 16K (fp16 x tile)
#define OFF_T   17408   // 2 x 16K
#define OFF_Y   50176   // 2 x (hi 4K + lo 4K)
#define SMEM_SZ 66560

// =====================================================================
// Precompute: trx -> fp16 + row norms (single pass), 16 threads per row
// =====================================================================
__global__ void k_prep(const float* __restrict__ trx) {
    int gid = blockIdx.x * blockDim.x + threadIdx.x;
    if (gid >= NPAD * 16) return;
    int row = gid >> 4, q = gid & 15;
    float4 v = make_float4(0.f, 0.f, 0.f, 0.f);
    if (row < NTRAIN) v = *(const float4*)(trx + (size_t)row * 64 + q * 4);
    size_t e = (size_t)row * 64 + q * 4;
    *(__half2*)(g_txb + e) = __floats2half2_rn(v.x, v.y);
    *(__half2*)(g_txb + e + 2) = __floats2half2_rn(v.z, v.w);
    float ss = v.x * v.x + v.y * v.y + v.z * v.z + v.w * v.w;
#pragma unroll
    for (int off = 1; off <= 8; off <<= 1)
        ss += __shfl_xor_sync(0xffffffffu, ss, off, 16);
    if (q == 0) g_tsq[row] = (row < NTRAIN) ? ss * K2f : -INFINITY;
}

__global__ void k_prepx(const float* __restrict__ x) {
    int gid = blockIdx.x * blockDim.x + threadIdx.x;
    if (gid >= BTOT * 16) return;
    int row = gid >> 4, q = gid & 15;
    float4 v = *(const float4*)(x + (size_t)row * 64 + q * 4);
    size_t e = (size_t)row * 64 + q * 4;
    *(__half2*)(g_xh + e) = __floats2half2_rn(v.x, v.y);
    *(__half2*)(g_xh + e + 2) = __floats2half2_rn(v.z, v.w);
    float ss = v.x * v.x + v.y * v.y + v.z * v.z + v.w * v.w;
#pragma unroll
    for (int off = 1; off <= 8; off <<= 1)
        ss += __shfl_xor_sync(0xffffffffu, ss, off, 16);
    if (q == 0) g_xsq[row] = ss * K2f;
}

__global__ void k_ty(const float* __restrict__ trY) {
    __shared__ __half shi[16][256];
    __shared__ __half slo[16][256];
    int n0 = blockIdx.x * 256;
    int t = threadIdx.x;
#pragma unroll
    for (int it = 0; it < 16; it++) {
        int e = t + it * 256;
        int r = e >> 4, c = e & 15;
        int row = n0 + r;
        float v = (row < NTRAIN) ? trY[(size_t)row * 16 + c] : 0.f;
        __half h = __float2half_rn(v);
        shi[c][r] = h;
        slo[c][r] = __float2half_rn(v - __half2float(h));
    }
    __syncthreads();
    if (n0 + t < NPAD) {
#pragma unroll
        for (int c = 0; c < 16; c++) {
            g_tyhi[(size_t)c * NPAD + n0 + t] = shi[c][t];
            g_tylo[(size_t)c * NPAD + n0 + t] = slo[c][t];
        }
    }
}

// =====================================================================
// Main fused kernel: per-n-pair fused GEMM1 -> exp -> GEMM2 (low reg, 2 CTA/SM)
// =====================================================================
__global__ void __launch_bounds__(256, 2) k_main() {
    extern __shared__ char smem[];
    const uint32_t sb = s2u(smem);
    const int t = threadIdx.x;
    const int wid = t >> 5, lane = t & 31;
    const int mbase = blockIdx.x * MT;
    const int s = blockIdx.y;

    // ldmatrix lane mapping
    const int l8 = lane & 7, lq = lane >> 3;
    const int lr = l8 + ((lq & 1) << 3);  // row within 16
    const int lh = lq >> 1;               // 16B column half

    // ---- prologue loads: x tile + chunk0 ----
#pragma unroll
    for (int i = 0; i < 4; i++) {
        int e = t + i * 256;
        int row = e >> 3, u = e & 7;
        cpa16(sb + OFF_X + SW(row * 128 + u * 16),
              g_xh + (size_t)(mbase + row) * 64 + u * 8);
    }
    auto load_chunk = [&](int ch, int b) {
        int nb = ch * BN;
#pragma unroll
        for (int i = 0; i < 4; i++) {
            int e = t + i * 256;
            int row = e >> 3, u = e & 7;
            cpa16(sb + OFF_T + b * 16384 + SW(row * 128 + u * 16),
                  g_txb + (size_t)(nb + row) * 64 + u * 8);
        }
#pragma unroll
        for (int i = 0; i < 2; i++) {
            int e = t + i * 256;
            int half = e >> 8, r = e & 255;
            int nblk = r >> 4, c = r & 15;
            const __half* src =
                (half ? g_tylo : g_tyhi) + (size_t)c * NPAD + nb + nblk * 8;
            cpa16(sb + OFF_Y + b * 8192 + half * 4096 + c * 256 +
                      (((uint32_t)(nblk ^ c)) << 4),
                  src);
        }
        if (t < 128) cpa4(sb + OFF_TSQ + b * 512 + t * 4, g_tsq + nb + t);
    };
    load_chunk(s, 0);
    cpcommit();
    cpwait0();
    __syncthreads();

    // ---- hoist A fragments (x fp16) into registers ----
    uint32_t ax[4][4];
#pragma unroll
    for (int kt = 0; kt < 4; kt++) {
        uint32_t o = SW((wid * 16 + lr) * 128 + kt * 32 + lh * 16);
        ldsm4(ax[kt], sb + OFF_X + o);
    }
    const int r0 = wid * 16 + (lane >> 2);
    const float xsk0 = g_xsq[mbase + r0];
    const float xsk1 = g_xsq[mbase + r0 + 8];

    float acc0[4] = {0.f, 0.f, 0.f, 0.f};  // pred channels 0-7
    float acc1[4] = {0.f, 0.f, 0.f, 0.f};  // pred channels 8-15
    float ws0 = 0.f, ws1 = 0.f;
    const int cc2 = 2 * (lane & 3);

    for (int ch = s, jj = 0; ch < NCH; ch += NSPLIT, jj++) {
        const int b = jj & 1;
        if (ch + NSPLIT < NCH) load_chunk(ch + NSPLIT, b ^ 1);
        cpcommit();

        const uint32_t tb = sb + OFF_T + b * 16384;
        const uint32_t tsb = sb + OFF_TSQ + b * 512;
        const uint32_t yb = sb + OFF_Y + b * 8192;

#pragma unroll
        for (int np = 0; np < 8; np++) {
            // ---- GEMM1 for the n-pair (tiles 2np, 2np+1) ----
            float c[2][4];
#pragma unroll
            for (int jn = 0; jn < 2; jn++)
#pragma unroll
                for (int q = 0; q < 4; q++) c[jn][q] = 0.f;
#pragma unroll
            for (int kt = 0; kt < 4; kt++) {
                uint32_t bt[4];
                ldsm4(bt, tb + SW((np * 16 + lr) * 128 + kt * 32 + lh * 16));
                mma16816(c[0], ax[kt], bt[0], bt[2]);
                mma16816(c[1], ax[kt], bt[1], bt[3]);
            }
            // ---- epilogue: weights -> fp16 A fragment ----
            uint32_t ah[4];
#pragma unroll
            for (int jn = 0; jn < 2; jn++) {
                const int j = 2 * np + jn;
                float2 tq = *(float2*)(smem + (tsb - sb) + (j * 8 + cc2) * 4);
                float w0 = ex2f(fmaf(c[jn][0], K1f, xsk0 + tq.x));
                float w1 = ex2f(fmaf(c[jn][1], K1f, xsk0 + tq.y));
                float w2 = ex2f(fmaf(c[jn][2], K1f, xsk1 + tq.x));
                float w3 = ex2f(fmaf(c[jn][3], K1f, xsk1 + tq.y));
                ws0 += w0 + w1;
                ws1 += w2 + w3;
                ah[jn * 2 + 0] = pack_hf(w1, w0);
                ah[jn * 2 + 1] = pack_hf(w3, w2);
            }
            // ---- GEMM2 for this n-k-tile ----
            uint32_t bh[4], bl[4];
            {
                uint32_t col = (uint32_t)((2 * np + lh) ^ lr) << 4;
                ldsm4(bh, yb + lr * 256 + col);
                ldsm4(bl, yb + 4096 + lr * 256 + col);
            }
            mma16816(acc0, ah, bh[0], bh[2]);
            mma16816(acc1, ah, bh[1], bh[3]);
            mma16816(acc0, ah, bl[0], bl[2]);
            mma16816(acc1, ah, bl[1], bl[3]);
        }

        cpwait0();
        __syncthreads();
    }

    // ---- store pred partials ----
    {
        float* p0 = g_pp + ((size_t)s * BTOT + mbase + r0) * CDIM;
        float* p1 = p0 + 8 * CDIM;
        const int cc = 2 * (lane & 3);
        *(float2*)(p0 + cc) = make_float2(acc0[0], acc0[1]);
        *(float2*)(p0 + 8 + cc) = make_float2(acc1[0], acc1[1]);
        *(float2*)(p1 + cc) = make_float2(acc0[2], acc0[3]);
        *(float2*)(p1 + 8 + cc) = make_float2(acc1[2], acc1[3]);
    }
    // ---- reduce row-sums across the 4 lanes sharing a row ----
#pragma unroll
    for (int off = 1; off <= 2; off <<= 1) {
        ws0 += __shfl_xor_sync(0xffffffffu, ws0, off);
        ws1 += __shfl_xor_sync(0xffffffffu, ws1, off);
    }
    if ((lane & 3) == 0) {
        g_ws[s * BTOT + mbase + r0] = ws0;
        g_ws[s * BTOT + mbase + r0 + 8] = ws1;
    }
}

// =====================================================================
// Reduce N-split partials + normalize
// =====================================================================
__global__ void k_fin(float* __restrict__ out) {
    int i = blockIdx.x * blockDim.x + threadIdx.x;
    if (i >= BTOT * CDIM) return;
    int qd = i >> 4;
    float acc = 0.f, wsum = 0.f;
#pragma unroll
    for (int s = 0; s < NSPLIT; s++) {
        acc += g_pp[(size_t)s * BTOT * CDIM + i];
        wsum += g_ws[s * BTOT + qd];
    }
    out[i] = acc / (wsum + 1e-10f);
}

extern "C" void kernel_launch(void* const* d_in, const int* in_sizes, int n_in,
                              void* d_out, int out_size) {
    const float* x   = (const float*)d_in[0];
    const float* trx = (const float*)d_in[1];
    const float* trY = (const float*)d_in[2];
    float* out = (float*)d_out;

    cudaFuncSetAttribute(k_main, cudaFuncAttributeMaxDynamicSharedMemorySize, SMEM_SZ);

    k_prep<<<(NPAD * 16 + 255) / 256, 256>>>(trx);
    k_prepx<<<(BTOT * 16 + 255) / 256, 256>>>(x);
    k_ty<<<(NPAD + 255) / 256, 256>>>(trY);
    dim3 grid(BTOT / MT, NSPLIT);
    k_main<<<grid, 256, SMEM_SZ>>>();
    k_fin<<<(BTOT * CDIM + 255) / 256, 256>>>(out);
}

// round 10
// speedup vs baseline: 9.1899x; 1.2104x over previous
#include <cuda_runtime.h>
#include <cuda_fp16.h>
#include <math.h>
#include <stdint.h>

#define BTOT 2048
#define NTRAIN 50000
#define NPAD 50048
#define BN 128
#define NCH 391            // NPAD / BN
#define NSPLIT 18
#define CDIM 16
#define MT 128

// exp(-d/(2*sigma^2)) = 2^( K1*(x.t) + K2*xsq + K2*tsq ); A pre-scaled by K1,
// norm terms folded into 4 augmented k-slots.
#define K1f 0.014426950408889634f     //  0.01  * log2(e)
#define K2f (-0.0072134752044448170f) // -0.005 * log2(e)

// ---------------- device scratch ----------------
__device__ __align__(16) __half g_txb[(size_t)NPAD * 64];   // trx fp16
__device__ __align__(16) __half g_taux[(size_t)NPAD * 8];   // [1,1,tsqK2hi,tsqK2lo,0..]
__device__ __align__(16) __half g_xh[(size_t)BTOT * 64];    // x * K1 fp16
__device__ __align__(16) __half g_xaux[(size_t)BTOT * 8];   // [xsqK2hi,xsqK2lo,1,1,0..]
__device__ __align__(16) __half g_tyhi[(size_t)CDIM * NPAD];
__device__ float g_pp[NSPLIT * BTOT * CDIM];
__device__ float g_ws[NSPLIT * BTOT];

// ---------------- helpers ----------------
static __device__ __forceinline__ uint32_t s2u(const void* p) {
    uint32_t a;
    asm("{ .reg .u64 t; cvta.to.shared.u64 t, %1; cvt.u32.u64 %0, t; }" : "=r"(a) : "l"(p));
    return a;
}
static __device__ __forceinline__ float ex2f(float x) {
    float r; asm("ex2.approx.ftz.f32 %0, %1;" : "=f"(r) : "f"(x)); return r;
}
static __device__ __forceinline__ void cpa16(uint32_t dst, const void* src) {
    asm volatile("cp.async.cg.shared.global [%0], [%1], 16;" :: "r"(dst), "l"(src));
}
static __device__ __forceinline__ void cpcommit() { asm volatile("cp.async.commit_group;"); }
static __device__ __forceinline__ void cpwait0() { asm volatile("cp.async.wait_group 0;"); }

static __device__ __forceinline__ void ldsm4(uint32_t* r, uint32_t addr) {
    asm volatile("ldmatrix.sync.aligned.m8n8.x4.shared.b16 {%0,%1,%2,%3}, [%4];"
                 : "=r"(r[0]), "=r"(r[1]), "=r"(r[2]), "=r"(r[3]) : "r"(addr));
}
static __device__ __forceinline__ void ldsm2(uint32_t* r, uint32_t addr) {
    asm volatile("ldmatrix.sync.aligned.m8n8.x2.shared.b16 {%0,%1}, [%2];"
                 : "=r"(r[0]), "=r"(r[1]) : "r"(addr));
}
static __device__ __forceinline__ void mma16816(float* d, const uint32_t* a,
                                                uint32_t b0, uint32_t b1) {
    asm volatile(
        "mma.sync.aligned.m16n8k16.row.col.f32.f16.f16.f32 "
        "{%0,%1,%2,%3}, {%4,%5,%6,%7}, {%8,%9}, {%0,%1,%2,%3};"
        : "+f"(d[0]), "+f"(d[1]), "+f"(d[2]), "+f"(d[3])
        : "r"(a[0]), "r"(a[1]), "r"(a[2]), "r"(a[3]), "r"(b0), "r"(b1));
}
static __device__ __forceinline__ void mma16808(float* d, uint32_t a0, uint32_t a1,
                                                uint32_t b0) {
    asm volatile(
        "mma.sync.aligned.m16n8k8.row.col.f32.f16.f16.f32 "
        "{%0,%1,%2,%3}, {%4,%5}, {%6}, {%0,%1,%2,%3};"
        : "+f"(d[0]), "+f"(d[1]), "+f"(d[2]), "+f"(d[3])
        : "r"(a0), "r"(a1), "r"(b0));
}
static __device__ __forceinline__ uint32_t pack_hf(float hi, float lo) {
    uint32_t r; asm("cvt.rn.f16x2.f32 %0, %1, %2;" : "=r"(r) : "f"(hi), "f"(lo));
    return r;
}

#define SW(o) ((uint32_t)(o) ^ ((((uint32_t)(o)) >> 3) & 0x70u))

// smem layout (bytes)
#define OFF_X   0       // 16K  x main tile
#define OFF_XA  16384   // 2K   x aux tile
#define OFF_T   18432   // 2 x 16K t main
#define OFF_TA  51200   // 2 x 2K  t aux
#define OFF_Y   55296   // 2 x 4K  Y (fp16 hi only)
#define SMEM_SZ 63488

// =====================================================================
// Precompute: trx -> fp16 + aux row (norm folded), 16 threads per row
// =====================================================================
__global__ void k_prep(const float* __restrict__ trx) {
    int gid = blockIdx.x * blockDim.x + threadIdx.x;
    if (gid >= NPAD * 16) return;
    int row = gid >> 4, q = gid & 15;
    float4 v = make_float4(0.f, 0.f, 0.f, 0.f);
    if (row < NTRAIN) v = *(const float4*)(trx + (size_t)row * 64 + q * 4);
    size_t e = (size_t)row * 64 + q * 4;
    *(__half2*)(g_txb + e) = __floats2half2_rn(v.x, v.y);
    *(__half2*)(g_txb + e + 2) = __floats2half2_rn(v.z, v.w);
    float ss = v.x * v.x + v.y * v.y + v.z * v.z + v.w * v.w;
#pragma unroll
    for (int off = 1; off <= 8; off <<= 1)
        ss += __shfl_xor_sync(0xffffffffu, ss, off, 16);
    if (q == 0) {
        __half hi, lo;
        if (row < NTRAIN) {
            float tq = ss * K2f;
            hi = __float2half_rn(tq);
            lo = __float2half_rn(tq - __half2float(hi));
        } else {
            hi = __float2half_rn(-60000.f);  // pad rows -> weight 0
            lo = __float2half_rn(0.f);
        }
        __half2* dst = (__half2*)(g_taux + (size_t)row * 8);
        dst[0] = __floats2half2_rn(1.f, 1.f);
        dst[1] = __halves2half2(hi, lo);
        dst[2] = __floats2half2_rn(0.f, 0.f);
        dst[3] = __floats2half2_rn(0.f, 0.f);
    }
}

__global__ void k_prepx(const float* __restrict__ x) {
    int gid = blockIdx.x * blockDim.x + threadIdx.x;
    if (gid >= BTOT * 16) return;
    int row = gid >> 4, q = gid & 15;
    float4 v = *(const float4*)(x + (size_t)row * 64 + q * 4);
    size_t e = (size_t)row * 64 + q * 4;
    *(__half2*)(g_xh + e) = __floats2half2_rn(v.x * K1f, v.y * K1f);
    *(__half2*)(g_xh + e + 2) = __floats2half2_rn(v.z * K1f, v.w * K1f);
    float ss = v.x * v.x + v.y * v.y + v.z * v.z + v.w * v.w;
#pragma unroll
    for (int off = 1; off <= 8; off <<= 1)
        ss += __shfl_xor_sync(0xffffffffu, ss, off, 16);
    if (q == 0) {
        float xq = ss * K2f;
        __half hi = __float2half_rn(xq);
        __half lo = __float2half_rn(xq - __half2float(hi));
        __half2* dst = (__half2*)(g_xaux + (size_t)row * 8);
        dst[0] = __halves2half2(hi, lo);
        dst[1] = __floats2half2_rn(1.f, 1.f);
        dst[2] = __floats2half2_rn(0.f, 0.f);
        dst[3] = __floats2half2_rn(0.f, 0.f);
    }
}

__global__ void k_ty(const float* __restrict__ trY) {
    __shared__ __half shi[16][256];
    int n0 = blockIdx.x * 256;
    int t = threadIdx.x;
#pragma unroll
    for (int it = 0; it < 16; it++) {
        int e = t + it * 256;
        int r = e >> 4, c = e & 15;
        int row = n0 + r;
        float v = (row < NTRAIN) ? trY[(size_t)row * 16 + c] : 0.f;
        shi[c][r] = __float2half_rn(v);
    }
    __syncthreads();
    if (n0 + t < NPAD) {
#pragma unroll
        for (int c = 0; c < 16; c++)
            g_tyhi[(size_t)c * NPAD + n0 + t] = shi[c][t];
    }
}

// =====================================================================
// Main: augmented GEMM1 (arg in accumulator) -> ex2 -> GEMM2 (Y fp16)
// =====================================================================
__global__ void __launch_bounds__(256, 2) k_main() {
    extern __shared__ char smem[];
    const uint32_t sb = s2u(smem);
    const int t = threadIdx.x;
    const int wid = t >> 5, lane = t & 31;
    const int mbase = blockIdx.x * MT;
    const int s = blockIdx.y;

    // ldmatrix lane mapping
    const int l8 = lane & 7, lq = lane >> 3;
    const int lr = l8 + ((lq & 1) << 3);  // row within 16
    const int lh = lq >> 1;               // 16B column half

    // ---- prologue: x main + x aux ----
#pragma unroll
    for (int i = 0; i < 4; i++) {
        int e = t + i * 256;
        int row = e >> 3, u = e & 7;
        cpa16(sb + OFF_X + SW(row * 128 + u * 16),
              g_xh + (size_t)(mbase + row) * 64 + u * 8);
    }
    if (t < 128)
        cpa16(sb + OFF_XA + t * 16, g_xaux + (size_t)(mbase + t) * 8);

    auto load_chunk = [&](int ch, int b) {
        int nb = ch * BN;
#pragma unroll
        for (int i = 0; i < 4; i++) {
            int e = t + i * 256;
            int row = e >> 3, u = e & 7;
            cpa16(sb + OFF_T + b * 16384 + SW(row * 128 + u * 16),
                  g_txb + (size_t)(nb + row) * 64 + u * 8);
        }
        if (t < 128)
            cpa16(sb + OFF_TA + b * 2048 + t * 16, g_taux + (size_t)(nb + t) * 8);
        {
            int nblk = t >> 4, c = t & 15;
            cpa16(sb + OFF_Y + b * 4096 + c * 256 + (((uint32_t)(nblk ^ c)) << 4),
                  g_tyhi + (size_t)c * NPAD + nb + nblk * 8);
        }
    };
    load_chunk(s, 0);
    cpcommit();
    cpwait0();
    __syncthreads();

    // ---- hoist A fragments: x main (4 k16) + x aux (1 k8) ----
    uint32_t ax[4][4], axa[2];
#pragma unroll
    for (int kt = 0; kt < 4; kt++) {
        uint32_t o = SW((wid * 16 + lr) * 128 + kt * 32 + lh * 16);
        ldsm4(ax[kt], sb + OFF_X + o);
    }
    ldsm2(axa, sb + OFF_XA + ((wid * 16 + (lane & 15)) << 4));

    const int r0 = wid * 16 + (lane >> 2);

    float acc0[4] = {0.f, 0.f, 0.f, 0.f};  // pred channels 0-7
    float acc1[4] = {0.f, 0.f, 0.f, 0.f};  // pred channels 8-15
    float ws0 = 0.f, ws1 = 0.f;

    for (int ch = s, jj = 0; ch < NCH; ch += NSPLIT, jj++) {
        const int b = jj & 1;
        if (ch + NSPLIT < NCH) load_chunk(ch + NSPLIT, b ^ 1);
        cpcommit();

        const uint32_t tb = sb + OFF_T + b * 16384;
        const uint32_t tab = sb + OFF_TA + b * 2048;
        const uint32_t yb = sb + OFF_Y + b * 4096;

#pragma unroll
        for (int np = 0; np < 8; np++) {
            // ---- GEMM1 (augmented): c = log2-weight directly ----
            float c[2][4];
#pragma unroll
            for (int jn = 0; jn < 2; jn++)
#pragma unroll
                for (int q = 0; q < 4; q++) c[jn][q] = 0.f;
#pragma unroll
            for (int kt = 0; kt < 4; kt++) {
                uint32_t bt[4];
                ldsm4(bt, tb + SW((np * 16 + lr) * 128 + kt * 32 + lh * 16));
                mma16816(c[0], ax[kt], bt[0], bt[2]);
                mma16816(c[1], ax[kt], bt[1], bt[3]);
            }
            {
                uint32_t bta[2];
                ldsm2(bta, tab + ((np * 16 + (lane & 15)) << 4));
                mma16808(c[0], axa[0], axa[1], bta[0]);
                mma16808(c[1], axa[0], axa[1], bta[1]);
            }
            // ---- epilogue: weights straight from accumulator ----
            uint32_t ah[4];
#pragma unroll
            for (int jn = 0; jn < 2; jn++) {
                float w0 = ex2f(c[jn][0]);
                float w1 = ex2f(c[jn][1]);
                float w2 = ex2f(c[jn][2]);
                float w3 = ex2f(c[jn][3]);
                ws0 += w0 + w1;
                ws1 += w2 + w3;
                ah[jn * 2 + 0] = pack_hf(w1, w0);
                ah[jn * 2 + 1] = pack_hf(w3, w2);
            }
            // ---- GEMM2 (single fp16 Y) ----
            uint32_t bh[4];
            {
                uint32_t col = (uint32_t)((2 * np + lh) ^ lr) << 4;
                ldsm4(bh, yb + lr * 256 + col);
            }
            mma16816(acc0, ah, bh[0], bh[2]);
            mma16816(acc1, ah, bh[1], bh[3]);
        }

        cpwait0();
        __syncthreads();
    }

    // ---- store pred partials ----
    {
        float* p0 = g_pp + ((size_t)s * BTOT + mbase + r0) * CDIM;
        float* p1 = p0 + 8 * CDIM;
        const int cc = 2 * (lane & 3);
        *(float2*)(p0 + cc) = make_float2(acc0[0], acc0[1]);
        *(float2*)(p0 + 8 + cc) = make_float2(acc1[0], acc1[1]);
        *(float2*)(p1 + cc) = make_float2(acc0[2], acc0[3]);
        *(float2*)(p1 + 8 + cc) = make_float2(acc1[2], acc1[3]);
    }
    // ---- reduce row-sums across the 4 lanes sharing a row ----
#pragma unroll
    for (int off = 1; off <= 2; off <<= 1) {
        ws0 += __shfl_xor_sync(0xffffffffu, ws0, off);
        ws1 += __shfl_xor_sync(0xffffffffu, ws1, off);
    }
    if ((lane & 3) == 0) {
        g_ws[s * BTOT + mbase + r0] = ws0;
        g_ws[s * BTOT + mbase + r0 + 8] = ws1;
    }
}

// =====================================================================
// Reduce N-split partials + normalize
// =====================================================================
__global__ void k_fin(float* __restrict__ out) {
    int i = blockIdx.x * blockDim.x + threadIdx.x;
    if (i >= BTOT * CDIM) return;
    int qd = i >> 4;
    float acc = 0.f, wsum = 0.f;
#pragma unroll
    for (int s = 0; s < NSPLIT; s++) {
        acc += g_pp[(size_t)s * BTOT * CDIM + i];
        wsum += g_ws[s * BTOT + qd];
    }
    out[i] = acc / (wsum + 1e-10f);
}

extern "C" void kernel_launch(void* const* d_in, const int* in_sizes, int n_in,
                              void* d_out, int out_size) {
    const float* x   = (const float*)d_in[0];
    const float* trx = (const float*)d_in[1];
    const float* trY = (const float*)d_in[2];
    float* out = (float*)d_out;

    cudaFuncSetAttribute(k_main, cudaFuncAttributeMaxDynamicSharedMemorySize, SMEM_SZ);

    k_prep<<<(NPAD * 16 + 255) / 256, 256>>>(trx);
    k_prepx<<<(BTOT * 16 + 255) / 256, 256>>>(x);
    k_ty<<<(NPAD + 255) / 256, 256>>>(trY);
    dim3 grid(BTOT / MT, NSPLIT);
    k_main<<<grid, 256, SMEM_SZ>>>();
    k_fin<<<(BTOT * CDIM + 255) / 256, 256>>>(out);
}

// round 11
// speedup vs baseline: 9.1937x; 1.0004x over previous
#include <cuda_runtime.h>
#include <cuda_fp16.h>
#include <math.h>
#include <stdint.h>

#define BTOT 2048
#define NTRAIN 50000
#define NPAD 50048
#define BN 128
#define NCH 391            // NPAD / BN
#define NSPLIT 18
#define CDIM 16
#define MT 128

// exp(-d/(2*sigma^2)) = 2^( K1*(x.t) + K2*xsq + K2*tsq ); A pre-scaled by K1,
// norm terms folded into 4 augmented k-slots.
#define K1f 0.014426950408889634f     //  0.01  * log2(e)
#define K2f (-0.0072134752044448170f) // -0.005 * log2(e)

// ---------------- device scratch ----------------
__device__ __align__(16) __half g_txb[(size_t)NPAD * 64];   // trx fp16
__device__ __align__(16) __half g_taux[(size_t)NPAD * 8];   // [1,1,tsqK2hi,tsqK2lo,0..]
__device__ __align__(16) __half g_xh[(size_t)BTOT * 64];    // x * K1 fp16
__device__ __align__(16) __half g_xaux[(size_t)BTOT * 8];   // [xsqK2hi,xsqK2lo,1,1,0..]
__device__ __align__(16) __half g_tyhi[(size_t)CDIM * NPAD];
__device__ float g_pp[NSPLIT * BTOT * CDIM];
__device__ float g_ws[NSPLIT * BTOT];

// ---------------- helpers ----------------
static __device__ __forceinline__ uint32_t s2u(const void* p) {
    uint32_t a;
    asm("{ .reg .u64 t; cvta.to.shared.u64 t, %1; cvt.u32.u64 %0, t; }" : "=r"(a) : "l"(p));
    return a;
}
static __device__ __forceinline__ void cpa16(uint32_t dst, const void* src) {
    asm volatile("cp.async.cg.shared.global [%0], [%1], 16;" :: "r"(dst), "l"(src));
}
static __device__ __forceinline__ void cpcommit() { asm volatile("cp.async.commit_group;"); }
static __device__ __forceinline__ void cpwait0() { asm volatile("cp.async.wait_group 0;"); }

static __device__ __forceinline__ void ldsm4(uint32_t* r, uint32_t addr) {
    asm volatile("ldmatrix.sync.aligned.m8n8.x4.shared.b16 {%0,%1,%2,%3}, [%4];"
                 : "=r"(r[0]), "=r"(r[1]), "=r"(r[2]), "=r"(r[3]) : "r"(addr));
}
static __device__ __forceinline__ void ldsm2(uint32_t* r, uint32_t addr) {
    asm volatile("ldmatrix.sync.aligned.m8n8.x2.shared.b16 {%0,%1}, [%2];"
                 : "=r"(r[0]), "=r"(r[1]) : "r"(addr));
}
static __device__ __forceinline__ void mma16816(float* d, const uint32_t* a,
                                                uint32_t b0, uint32_t b1) {
    asm volatile(
        "mma.sync.aligned.m16n8k16.row.col.f32.f16.f16.f32 "
        "{%0,%1,%2,%3}, {%4,%5,%6,%7}, {%8,%9}, {%0,%1,%2,%3};"
        : "+f"(d[0]), "+f"(d[1]), "+f"(d[2]), "+f"(d[3])
        : "r"(a[0]), "r"(a[1]), "r"(a[2]), "r"(a[3]), "r"(b0), "r"(b1));
}
static __device__ __forceinline__ void mma16808(float* d, uint32_t a0, uint32_t a1,
                                                uint32_t b0) {
    asm volatile(
        "mma.sync.aligned.m16n8k8.row.col.f32.f16.f16.f32 "
        "{%0,%1,%2,%3}, {%4,%5}, {%6}, {%0,%1,%2,%3};"
        : "+f"(d[0]), "+f"(d[1]), "+f"(d[2]), "+f"(d[3])
        : "r"(a0), "r"(a1), "r"(b0));
}
static __device__ __forceinline__ uint32_t pack_hf(float hi, float lo) {
    uint32_t r; asm("cvt.rn.f16x2.f32 %0, %1, %2;" : "=r"(r) : "f"(hi), "f"(lo));
    return r;
}
static __device__ __forceinline__ uint32_t ex2h2(uint32_t a) {
    uint32_t r; asm("ex2.approx.f16x2 %0, %1;" : "=r"(r) : "r"(a));
    return r;
}

#define SW(o) ((uint32_t)(o) ^ ((((uint32_t)(o)) >> 3) & 0x70u))

// smem layout (bytes)
#define OFF_X   0       // 16K  x main tile
#define OFF_XA  16384   // 2K   x aux tile
#define OFF_T   18432   // 2 x 16K t main
#define OFF_TA  51200   // 2 x 2K  t aux
#define OFF_Y   55296   // 2 x 4K  Y (fp16)
#define SMEM_SZ 63488

// =====================================================================
// Merged precompute: [trx fp16+aux | x fp16+aux | trY transpose]
// =====================================================================
#define NB_T ((NPAD * 16 + 255) / 256)   // 3128
#define NB_X ((BTOT * 16 + 255) / 256)   // 128
#define NB_Y ((NPAD + 255) / 256)        // 196

__global__ void k_pre(const float* __restrict__ trx, const float* __restrict__ x,
                      const float* __restrict__ trY) {
    __shared__ __half shi[16][256];
    int bx = blockIdx.x;
    int t = threadIdx.x;
    if (bx < NB_T) {
        int gid = bx * 256 + t;
        if (gid >= NPAD * 16) return;
        int row = gid >> 4, q = gid & 15;
        float4 v = make_float4(0.f, 0.f, 0.f, 0.f);
        if (row < NTRAIN) v = *(const float4*)(trx + (size_t)row * 64 + q * 4);
        size_t e = (size_t)row * 64 + q * 4;
        *(__half2*)(g_txb + e) = __floats2half2_rn(v.x, v.y);
        *(__half2*)(g_txb + e + 2) = __floats2half2_rn(v.z, v.w);
        float ss = v.x * v.x + v.y * v.y + v.z * v.z + v.w * v.w;
#pragma unroll
        for (int off = 1; off <= 8; off <<= 1)
            ss += __shfl_xor_sync(0xffffffffu, ss, off, 16);
        if (q == 0) {
            __half hi, lo;
            if (row < NTRAIN) {
                float tq = ss * K2f;
                hi = __float2half_rn(tq);
                lo = __float2half_rn(tq - __half2float(hi));
            } else {
                hi = __float2half_rn(-60000.f);  // pad rows -> weight 0
                lo = __float2half_rn(0.f);
            }
            __half2* dst = (__half2*)(g_taux + (size_t)row * 8);
            dst[0] = __floats2half2_rn(1.f, 1.f);
            dst[1] = __halves2half2(hi, lo);
            dst[2] = __floats2half2_rn(0.f, 0.f);
            dst[3] = __floats2half2_rn(0.f, 0.f);
        }
    } else if (bx < NB_T + NB_X) {
        int gid = (bx - NB_T) * 256 + t;
        if (gid >= BTOT * 16) return;
        int row = gid >> 4, q = gid & 15;
        float4 v = *(const float4*)(x + (size_t)row * 64 + q * 4);
        size_t e = (size_t)row * 64 + q * 4;
        *(__half2*)(g_xh + e) = __floats2half2_rn(v.x * K1f, v.y * K1f);
        *(__half2*)(g_xh + e + 2) = __floats2half2_rn(v.z * K1f, v.w * K1f);
        float ss = v.x * v.x + v.y * v.y + v.z * v.z + v.w * v.w;
#pragma unroll
        for (int off = 1; off <= 8; off <<= 1)
            ss += __shfl_xor_sync(0xffffffffu, ss, off, 16);
        if (q == 0) {
            float xq = ss * K2f;
            __half hi = __float2half_rn(xq);
            __half lo = __float2half_rn(xq - __half2float(hi));
            __half2* dst = (__half2*)(g_xaux + (size_t)row * 8);
            dst[0] = __halves2half2(hi, lo);
            dst[1] = __floats2half2_rn(1.f, 1.f);
            dst[2] = __floats2half2_rn(0.f, 0.f);
            dst[3] = __floats2half2_rn(0.f, 0.f);
        }
    } else {
        int n0 = (bx - NB_T - NB_X) * 256;
#pragma unroll
        for (int it = 0; it < 16; it++) {
            int e = t + it * 256;
            int r = e >> 4, c = e & 15;
            int row = n0 + r;
            float v = (row < NTRAIN) ? trY[(size_t)row * 16 + c] : 0.f;
            shi[c][r] = __float2half_rn(v);
        }
        __syncthreads();
        if (n0 + t < NPAD) {
#pragma unroll
            for (int c = 0; c < 16; c++)
                g_tyhi[(size_t)c * NPAD + n0 + t] = shi[c][t];
        }
    }
}

// =====================================================================
// Main: augmented GEMM1 -> ex2.f16x2 -> GEMM2 (+ tensorized weight sum)
// =====================================================================
__global__ void __launch_bounds__(256, 2) k_main() {
    extern __shared__ char smem[];
    const uint32_t sb = s2u(smem);
    const int t = threadIdx.x;
    const int wid = t >> 5, lane = t & 31;
    const int mbase = blockIdx.x * MT;
    const int s = blockIdx.y;

    // ldmatrix lane mapping
    const int l8 = lane & 7, lq = lane >> 3;
    const int lr = l8 + ((lq & 1) << 3);  // row within 16
    const int lh = lq >> 1;               // 16B column half

    // ones B-fragment for the weight-sum column (n=0 all-ones, others 0)
    const uint32_t bones = (lane < 4) ? 0x3C003C00u : 0u;

    // ---- prologue: x main + x aux ----
#pragma unroll
    for (int i = 0; i < 4; i++) {
        int e = t + i * 256;
        int row = e >> 3, u = e & 7;
        cpa16(sb + OFF_X + SW(row * 128 + u * 16),
              g_xh + (size_t)(mbase + row) * 64 + u * 8);
    }
    if (t < 128)
        cpa16(sb + OFF_XA + t * 16, g_xaux + (size_t)(mbase + t) * 8);

    auto load_chunk = [&](int ch, int b) {
        int nb = ch * BN;
#pragma unroll
        for (int i = 0; i < 4; i++) {
            int e = t + i * 256;
            int row = e >> 3, u = e & 7;
            cpa16(sb + OFF_T + b * 16384 + SW(row * 128 + u * 16),
                  g_txb + (size_t)(nb + row) * 64 + u * 8);
        }
        if (t < 128)
            cpa16(sb + OFF_TA + b * 2048 + t * 16, g_taux + (size_t)(nb + t) * 8);
        {
            int nblk = t >> 4, c = t & 15;
            cpa16(sb + OFF_Y + b * 4096 + c * 256 + (((uint32_t)(nblk ^ c)) << 4),
                  g_tyhi + (size_t)c * NPAD + nb + nblk * 8);
        }
    };
    load_chunk(s, 0);
    cpcommit();
    cpwait0();
    __syncthreads();

    // ---- hoist A fragments: x main (4 k16) + x aux (1 k8) ----
    uint32_t ax[4][4], axa[2];
#pragma unroll
    for (int kt = 0; kt < 4; kt++) {
        uint32_t o = SW((wid * 16 + lr) * 128 + kt * 32 + lh * 16);
        ldsm4(ax[kt], sb + OFF_X + o);
    }
    ldsm2(axa, sb + OFF_XA + ((wid * 16 + (lane & 15)) << 4));

    const int r0 = wid * 16 + (lane >> 2);

    float acc0[4] = {0.f, 0.f, 0.f, 0.f};  // pred channels 0-7
    float acc1[4] = {0.f, 0.f, 0.f, 0.f};  // pred channels 8-15
    float acc2[4] = {0.f, 0.f, 0.f, 0.f};  // weight sum (ones column)

    for (int ch = s, jj = 0; ch < NCH; ch += NSPLIT, jj++) {
        const int b = jj & 1;
        if (ch + NSPLIT < NCH) load_chunk(ch + NSPLIT, b ^ 1);
        cpcommit();

        const uint32_t tb = sb + OFF_T + b * 16384;
        const uint32_t tab = sb + OFF_TA + b * 2048;
        const uint32_t yb = sb + OFF_Y + b * 4096;

#pragma unroll
        for (int np = 0; np < 8; np++) {
            // ---- GEMM1 (augmented): c = log2-weight directly ----
            float c[2][4];
#pragma unroll
            for (int jn = 0; jn < 2; jn++)
#pragma unroll
                for (int q = 0; q < 4; q++) c[jn][q] = 0.f;
#pragma unroll
            for (int kt = 0; kt < 4; kt++) {
                uint32_t bt[4];
                ldsm4(bt, tb + SW((np * 16 + lr) * 128 + kt * 32 + lh * 16));
                mma16816(c[0], ax[kt], bt[0], bt[2]);
                mma16816(c[1], ax[kt], bt[1], bt[3]);
            }
            {
                uint32_t bta[2];
                ldsm2(bta, tab + ((np * 16 + (lane & 15)) << 4));
                mma16808(c[0], axa[0], axa[1], bta[0]);
                mma16808(c[1], axa[0], axa[1], bta[1]);
            }
            // ---- epilogue: weights via vector ex2 (A fragment directly) ----
            uint32_t ah[4];
#pragma unroll
            for (int jn = 0; jn < 2; jn++) {
                ah[jn * 2 + 0] = ex2h2(pack_hf(c[jn][1], c[jn][0]));
                ah[jn * 2 + 1] = ex2h2(pack_hf(c[jn][3], c[jn][2]));
            }
            // ---- GEMM2 + tensorized weight sum ----
            uint32_t bh[4];
            {
                uint32_t col = (uint32_t)((2 * np + lh) ^ lr) << 4;
                ldsm4(bh, yb + lr * 256 + col);
            }
            mma16816(acc0, ah, bh[0], bh[2]);
            mma16816(acc1, ah, bh[1], bh[3]);
            mma16816(acc2, ah, bones, bones);
        }

        cpwait0();
        __syncthreads();
    }

    // ---- store pred partials ----
    {
        float* p0 = g_pp + ((size_t)s * BTOT + mbase + r0) * CDIM;
        float* p1 = p0 + 8 * CDIM;
        const int cc = 2 * (lane & 3);
        *(float2*)(p0 + cc) = make_float2(acc0[0], acc0[1]);
        *(float2*)(p0 + 8 + cc) = make_float2(acc1[0], acc1[1]);
        *(float2*)(p1 + cc) = make_float2(acc0[2], acc0[3]);
        *(float2*)(p1 + 8 + cc) = make_float2(acc1[2], acc1[3]);
    }
    // ---- weight sums live in the ones column (lanes with lane%4==0) ----
    if ((lane & 3) == 0) {
        g_ws[s * BTOT + mbase + r0] = acc2[0];
        g_ws[s * BTOT + mbase + r0 + 8] = acc2[2];
    }
}

// =====================================================================
// Reduce N-split partials + normalize
// =====================================================================
__global__ void k_fin(float* __restrict__ out) {
    int i = blockIdx.x * blockDim.x + threadIdx.x;
    if (i >= BTOT * CDIM) return;
    int qd = i >> 4;
    float acc = 0.f, wsum = 0.f;
#pragma unroll
    for (int s = 0; s < NSPLIT; s++) {
        acc += g_pp[(size_t)s * BTOT * CDIM + i];
        wsum += g_ws[s * BTOT + qd];
    }
    out[i] = acc / (wsum + 1e-10f);
}

extern "C" void kernel_launch(void* const* d_in, const int* in_sizes, int n_in,
                              void* d_out, int out_size) {
    const float* x   = (const float*)d_in[0];
    const float* trx = (const float*)d_in[1];
    const float* trY = (const float*)d_in[2];
    float* out = (float*)d_out;

    cudaFuncSetAttribute(k_main, cudaFuncAttributeMaxDynamicSharedMemorySize, SMEM_SZ);

    k_pre<<<NB_T + NB_X + NB_Y, 256>>>(trx, x, trY);
    dim3 grid(BTOT / MT, NSPLIT);
    k_main<<<grid, 256, SMEM_SZ>>>();
    k_fin<<<(BTOT * CDIM + 255) / 256, 256>>>(out);
}

// round 13
// speedup vs baseline: 9.5633x; 1.0402x over previous
#include <cuda_runtime.h>
#include <cuda_fp16.h>
#include <math.h>
#include <stdint.h>

#define BTOT 2048
#define NTRAIN 50000
#define NPAD 50048
#define BN 128
#define NCH 391            // NPAD / BN
#define NSPLIT 18
#define CDIM 16
#define MT 128

// exp(-d/(2*sigma^2)) = 2^( K1*(x.t) + K2*xsq + K2*tsq ); A pre-scaled by K1,
// norm terms folded into 4 augmented k-slots.
#define K1f 0.014426950408889634f     //  0.01  * log2(e)
#define K2f (-0.0072134752044448170f) // -0.005 * log2(e)

// ---------------- device scratch ----------------
__device__ __align__(16) __half g_txb[(size_t)NPAD * 64];   // trx fp16
__device__ __align__(16) __half g_taux[(size_t)NPAD * 8];   // [1,1,tsqK2hi,tsqK2lo,0..]
__device__ __align__(16) __half g_xh[(size_t)BTOT * 64];    // x * K1 fp16
__device__ __align__(16) __half g_xaux[(size_t)BTOT * 8];   // [xsqK2hi,xsqK2lo,1,1,0..]
__device__ __align__(16) __half g_tyhi[(size_t)CDIM * NPAD];
__device__ float g_pp[NSPLIT * BTOT * CDIM];
__device__ float g_ws[NSPLIT * BTOT];

// ---------------- helpers ----------------
static __device__ __forceinline__ uint32_t s2u(const void* p) {
    uint32_t a;
    asm("{ .reg .u64 t; cvta.to.shared.u64 t, %1; cvt.u32.u64 %0, t; }" : "=r"(a) : "l"(p));
    return a;
}
static __device__ __forceinline__ void cpa16(uint32_t dst, const void* src) {
    asm volatile("cp.async.cg.shared.global [%0], [%1], 16;" :: "r"(dst), "l"(src));
}
static __device__ __forceinline__ void cpcommit() { asm volatile("cp.async.commit_group;"); }
static __device__ __forceinline__ void cpwait0() { asm volatile("cp.async.wait_group 0;"); }

static __device__ __forceinline__ void ldsm4(uint32_t* r, uint32_t addr) {
    asm volatile("ldmatrix.sync.aligned.m8n8.x4.shared.b16 {%0,%1,%2,%3}, [%4];"
                 : "=r"(r[0]), "=r"(r[1]), "=r"(r[2]), "=r"(r[3]) : "r"(addr));
}
static __device__ __forceinline__ void ldsm2(uint32_t* r, uint32_t addr) {
    asm volatile("ldmatrix.sync.aligned.m8n8.x2.shared.b16 {%0,%1}, [%2];"
                 : "=r"(r[0]), "=r"(r[1]) : "r"(addr));
}
static __device__ __forceinline__ void mma16816(float* d, const uint32_t* a,
                                                uint32_t b0, uint32_t b1) {
    asm volatile(
        "mma.sync.aligned.m16n8k16.row.col.f32.f16.f16.f32 "
        "{%0,%1,%2,%3}, {%4,%5,%6,%7}, {%8,%9}, {%0,%1,%2,%3};"
        : "+f"(d[0]), "+f"(d[1]), "+f"(d[2]), "+f"(d[3])
        : "r"(a[0]), "r"(a[1]), "r"(a[2]), "r"(a[3]), "r"(b0), "r"(b1));
}
static __device__ __forceinline__ void mma16808(float* d, uint32_t a0, uint32_t a1,
                                                uint32_t b0) {
    asm volatile(
        "mma.sync.aligned.m16n8k8.row.col.f32.f16.f16.f32 "
        "{%0,%1,%2,%3}, {%4,%5}, {%6}, {%0,%1,%2,%3};"
        : "+f"(d[0]), "+f"(d[1]), "+f"(d[2]), "+f"(d[3])
        : "r"(a0), "r"(a1), "r"(b0));
}
static __device__ __forceinline__ uint32_t pack_hf(float hi, float lo) {
    uint32_t r; asm("cvt.rn.f16x2.f32 %0, %1, %2;" : "=r"(r) : "f"(hi), "f"(lo));
    return r;
}
static __device__ __forceinline__ uint32_t ex2h2(uint32_t a) {
    uint32_t r; asm("ex2.approx.f16x2 %0, %1;" : "=r"(r) : "r"(a));
    return r;
}

#define SW(o) ((uint32_t)(o) ^ ((((uint32_t)(o)) >> 3) & 0x70u))

// smem layout (bytes)
#define OFF_X   0       // 16K  x main tile
#define OFF_XA  16384   // 2K   x aux tile
#define OFF_T   18432   // 2 x 16K t main
#define OFF_TA  51200   // 2 x 2K  t aux
#define OFF_Y   55296   // 2 x 4K  Y (fp16)
#define SMEM_SZ 63488

// =====================================================================
// Merged precompute, MLP=4 variant: 4 threads per row, 4 float4 loads each
// =====================================================================
#define NB_T ((NPAD * 4) / 256)          // 782
#define NB_X ((BTOT * 4) / 256)          // 32
#define NB_Y ((NPAD + 255) / 256)        // 196

__global__ void k_pre(const float* __restrict__ trx, const float* __restrict__ x,
                      const float* __restrict__ trY) {
    __shared__ __half shi[16][256];
    int bx = blockIdx.x;
    int t = threadIdx.x;
    if (bx < NB_T + NB_X) {
        const bool isx = (bx >= NB_T);
        int gid = (isx ? (bx - NB_T) : bx) * 256 + t;
        int row = gid >> 2, q = gid & 3;
        const float* src = isx ? (x + (size_t)row * 64) : (trx + (size_t)row * 64);
        const bool valid = isx || (row < NTRAIN);
        // 4 independent float4 loads (MLP = 4)
        float4 v[4];
#pragma unroll
        for (int i = 0; i < 4; i++) {
            v[i] = make_float4(0.f, 0.f, 0.f, 0.f);
            if (valid) v[i] = *(const float4*)(src + (q + 4 * i) * 4);
        }
        float ss = 0.f;
#pragma unroll
        for (int i = 0; i < 4; i++)
            ss += v[i].x * v[i].x + v[i].y * v[i].y + v[i].z * v[i].z + v[i].w * v[i].w;
        // store fp16 (x side pre-scaled by K1)
        const float sc = isx ? K1f : 1.f;
        __half* dstm = isx ? g_xh : g_txb;
#pragma unroll
        for (int i = 0; i < 4; i++) {
            size_t e = (size_t)row * 64 + (q + 4 * i) * 4;
            *(__half2*)(dstm + e) = __floats2half2_rn(v[i].x * sc, v[i].y * sc);
            *(__half2*)(dstm + e + 2) = __floats2half2_rn(v[i].z * sc, v[i].w * sc);
        }
        // norm reduce across the 4 lanes of this row
        ss += __shfl_xor_sync(0xffffffffu, ss, 1, 4);
        ss += __shfl_xor_sync(0xffffffffu, ss, 2, 4);
        if (q == 0) {
            if (isx) {
                float xq = ss * K2f;
                __half hi = __float2half_rn(xq);
                __half lo = __float2half_rn(xq - __half2float(hi));
                __half2* dst = (__half2*)(g_xaux + (size_t)row * 8);
                dst[0] = __halves2half2(hi, lo);
                dst[1] = __floats2half2_rn(1.f, 1.f);
                dst[2] = __floats2half2_rn(0.f, 0.f);
                dst[3] = __floats2half2_rn(0.f, 0.f);
            } else {
                __half hi, lo;
                if (valid) {
                    float tq = ss * K2f;
                    hi = __float2half_rn(tq);
                    lo = __float2half_rn(tq - __half2float(hi));
                } else {
                    hi = __float2half_rn(-60000.f);  // pad rows -> weight 0
                    lo = __float2half_rn(0.f);
                }
                __half2* dst = (__half2*)(g_taux + (size_t)row * 8);
                dst[0] = __floats2half2_rn(1.f, 1.f);
                dst[1] = __halves2half2(hi, lo);
                dst[2] = __floats2half2_rn(0.f, 0.f);
                dst[3] = __floats2half2_rn(0.f, 0.f);
            }
        }
    } else {
        int n0 = (bx - NB_T - NB_X) * 256;
#pragma unroll
        for (int it = 0; it < 16; it++) {
            int e = t + it * 256;
            int r = e >> 4, c = e & 15;
            int row = n0 + r;
            float v = (row < NTRAIN) ? trY[(size_t)row * 16 + c] : 0.f;
            shi[c][r] = __float2half_rn(v);
        }
        __syncthreads();
        if (n0 + t < NPAD) {
#pragma unroll
            for (int c = 0; c < 16; c++)
                g_tyhi[(size_t)c * NPAD + n0 + t] = shi[c][t];
        }
    }
}

// =====================================================================
// Main: augmented GEMM1 -> ex2.f16x2 -> GEMM2 (+ tensorized weight sum)
// =====================================================================
__global__ void __launch_bounds__(256, 2) k_main() {
    extern __shared__ char smem[];
    const uint32_t sb = s2u(smem);
    const int t = threadIdx.x;
    const int wid = t >> 5, lane = t & 31;
    const int mbase = blockIdx.x * MT;
    const int s = blockIdx.y;

    // ldmatrix lane mapping
    const int l8 = lane & 7, lq = lane >> 3;
    const int lr = l8 + ((lq & 1) << 3);  // row within 16
    const int lh = lq >> 1;               // 16B column half

    // ones B-fragment for the weight-sum column (n=0 all-ones, others 0)
    const uint32_t bones = (lane < 4) ? 0x3C003C00u : 0u;

    // ---- prologue: x main + x aux ----
#pragma unroll
    for (int i = 0; i < 4; i++) {
        int e = t + i * 256;
        int row = e >> 3, u = e & 7;
        cpa16(sb + OFF_X + SW(row * 128 + u * 16),
              g_xh + (size_t)(mbase + row) * 64 + u * 8);
    }
    if (t < 128)
        cpa16(sb + OFF_XA + t * 16, g_xaux + (size_t)(mbase + t) * 8);

    auto load_chunk = [&](int ch, int b) {
        int nb = ch * BN;
#pragma unroll
        for (int i = 0; i < 4; i++) {
            int e = t + i * 256;
            int row = e >> 3, u = e & 7;
            cpa16(sb + OFF_T + b * 16384 + SW(row * 128 + u * 16),
                  g_txb + (size_t)(nb + row) * 64 + u * 8);
        }
        if (t < 128)
            cpa16(sb + OFF_TA + b * 2048 + t * 16, g_taux + (size_t)(nb + t) * 8);
        {
            int nblk = t >> 4, c = t & 15;
            cpa16(sb + OFF_Y + b * 4096 + c * 256 + (((uint32_t)(nblk ^ c)) << 4),
                  g_tyhi + (size_t)c * NPAD + nb + nblk * 8);
        }
    };
    load_chunk(s, 0);
    cpcommit();
    cpwait0();
    __syncthreads();

    // ---- hoist A fragments: x main (4 k16) + x aux (1 k8) ----
    uint32_t ax[4][4], axa[2];
#pragma unroll
    for (int kt = 0; kt < 4; kt++) {
        uint32_t o = SW((wid * 16 + lr) * 128 + kt * 32 + lh * 16);
        ldsm4(ax[kt], sb + OFF_X + o);
    }
    ldsm2(axa, sb + OFF_XA + ((wid * 16 + (lane & 15)) << 4));

    const int r0 = wid * 16 + (lane >> 2);

    float acc0[4] = {0.f, 0.f, 0.f, 0.f};  // pred channels 0-7
    float acc1[4] = {0.f, 0.f, 0.f, 0.f};  // pred channels 8-15
    float acc2[4] = {0.f, 0.f, 0.f, 0.f};  // weight sum (ones column)

    for (int ch = s, jj = 0; ch < NCH; ch += NSPLIT, jj++) {
        const int b = jj & 1;
        if (ch + NSPLIT < NCH) load_chunk(ch + NSPLIT, b ^ 1);
        cpcommit();

        const uint32_t tb = sb + OFF_T + b * 16384;
        const uint32_t tab = sb + OFF_TA + b * 2048;
        const uint32_t yb = sb + OFF_Y + b * 4096;

#pragma unroll
        for (int np = 0; np < 8; np++) {
            // ---- GEMM1 (augmented): c = log2-weight directly ----
            float c[2][4];
#pragma unroll
            for (int jn = 0; jn < 2; jn++)
#pragma unroll
                for (int q = 0; q < 4; q++) c[jn][q] = 0.f;
#pragma unroll
            for (int kt = 0; kt < 4; kt++) {
                uint32_t bt[4];
                ldsm4(bt, tb + SW((np * 16 + lr) * 128 + kt * 32 + lh * 16));
                mma16816(c[0], ax[kt], bt[0], bt[2]);
                mma16816(c[1], ax[kt], bt[1], bt[3]);
            }
            {
                uint32_t bta[2];
                ldsm2(bta, tab + ((np * 16 + (lane & 15)) << 4));
                mma16808(c[0], axa[0], axa[1], bta[0]);
                mma16808(c[1], axa[0], axa[1], bta[1]);
            }
            // ---- epilogue: weights via vector ex2 (A fragment directly) ----
            uint32_t ah[4];
#pragma unroll
            for (int jn = 0; jn < 2; jn++) {
                ah[jn * 2 + 0] = ex2h2(pack_hf(c[jn][1], c[jn][0]));
                ah[jn * 2 + 1] = ex2h2(pack_hf(c[jn][3], c[jn][2]));
            }
            // ---- GEMM2 + tensorized weight sum ----
            uint32_t bh[4];
            {
                uint32_t col = (uint32_t)((2 * np + lh) ^ lr) << 4;
                ldsm4(bh, yb + lr * 256 + col);
            }
            mma16816(acc0, ah, bh[0], bh[2]);
            mma16816(acc1, ah, bh[1], bh[3]);
            mma16816(acc2, ah, bones, bones);
        }

        cpwait0();
        __syncthreads();
    }

    // ---- store pred partials ----
    {
        float* p0 = g_pp + ((size_t)s * BTOT + mbase + r0) * CDIM;
        float* p1 = p0 + 8 * CDIM;
        const int cc = 2 * (lane & 3);
        *(float2*)(p0 + cc) = make_float2(acc0[0], acc0[1]);
        *(float2*)(p0 + 8 + cc) = make_float2(acc1[0], acc1[1]);
        *(float2*)(p1 + cc) = make_float2(acc0[2], acc0[3]);
        *(float2*)(p1 + 8 + cc) = make_float2(acc1[2], acc1[3]);
    }
    // ---- weight sums live in the ones column (lanes with lane%4==0) ----
    if ((lane & 3) == 0) {
        g_ws[s * BTOT + mbase + r0] = acc2[0];
        g_ws[s * BTOT + mbase + r0 + 8] = acc2[2];
    }
}

// =====================================================================
// Reduce N-split partials + normalize
// =====================================================================
__global__ void k_fin(float* __restrict__ out) {
    int i = blockIdx.x * blockDim.x + threadIdx.x;
    if (i >= BTOT * CDIM) return;
    int qd = i >> 4;
    float acc = 0.f, wsum = 0.f;
#pragma unroll
    for (int s = 0; s < NSPLIT; s++) {
        acc += g_pp[(size_t)s * BTOT * CDIM + i];
        wsum += g_ws[s * BTOT + qd];
    }
    out[i] = acc / (wsum + 1e-10f);
}

extern "C" void kernel_launch(void* const* d_in, const int* in_sizes, int n_in,
                              void* d_out, int out_size) {
    const float* x   = (const float*)d_in[0];
    const float* trx = (const float*)d_in[1];
    const float* trY = (const float*)d_in[2];
    float* out = (float*)d_out;

    cudaFuncSetAttribute(k_main, cudaFuncAttributeMaxDynamicSharedMemorySize, SMEM_SZ);

    k_pre<<<NB_T + NB_X + NB_Y, 256>>>(trx, x, trY);
    dim3 grid(BTOT / MT, NSPLIT);
    k_main<<<grid, 256, SMEM_SZ>>>();
    k_fin<<<(BTOT * CDIM + 255) / 256, 256>>>(out);
}

// round 14
// speedup vs baseline: 10.5417x; 1.1023x over previous
#include <cuda_runtime.h>
#include <cuda_fp16.h>
#include <math.h>
#include <stdint.h>

#define BTOT 2048
#define NTRAIN 50000
#define NPAD 50048
#define BN 128
#define NCH 391            // NPAD / BN
#define NSPLIT 18
#define CDIM 16
#define MT 256

// exp(-d/(2*sigma^2)) = 2^( K1*(x.t) + K2*xsq + K2*tsq ); A pre-scaled by K1,
// norm terms folded into 4 augmented k-slots.
#define K1f 0.014426950408889634f     //  0.01  * log2(e)
#define K2f (-0.0072134752044448170f) // -0.005 * log2(e)

// ---------------- device scratch ----------------
__device__ __align__(16) __half g_txb[(size_t)NPAD * 64];   // trx fp16
__device__ __align__(16) __half g_taux[(size_t)NPAD * 8];   // [1,1,tsqK2hi,tsqK2lo,0..]
__device__ __align__(16) __half g_xh[(size_t)BTOT * 64];    // x * K1 fp16
__device__ __align__(16) __half g_xaux[(size_t)BTOT * 8];   // [xsqK2hi,xsqK2lo,1,1,0..]
__device__ __align__(16) __half g_tyhi[(size_t)CDIM * NPAD];
__device__ float g_pp[NSPLIT * BTOT * CDIM];
__device__ float g_ws[NSPLIT * BTOT];

// ---------------- helpers ----------------
static __device__ __forceinline__ uint32_t s2u(const void* p) {
    uint32_t a;
    asm("{ .reg .u64 t; cvta.to.shared.u64 t, %1; cvt.u32.u64 %0, t; }" : "=r"(a) : "l"(p));
    return a;
}
static __device__ __forceinline__ void cpa16(uint32_t dst, const void* src) {
    asm volatile("cp.async.cg.shared.global [%0], [%1], 16;" :: "r"(dst), "l"(src));
}
static __device__ __forceinline__ void cpcommit() { asm volatile("cp.async.commit_group;"); }
static __device__ __forceinline__ void cpwait0() { asm volatile("cp.async.wait_group 0;"); }

static __device__ __forceinline__ void ldsm4(uint32_t* r, uint32_t addr) {
    asm volatile("ldmatrix.sync.aligned.m8n8.x4.shared.b16 {%0,%1,%2,%3}, [%4];"
                 : "=r"(r[0]), "=r"(r[1]), "=r"(r[2]), "=r"(r[3]) : "r"(addr));
}
static __device__ __forceinline__ void ldsm2(uint32_t* r, uint32_t addr) {
    asm volatile("ldmatrix.sync.aligned.m8n8.x2.shared.b16 {%0,%1}, [%2];"
                 : "=r"(r[0]), "=r"(r[1]) : "r"(addr));
}
static __device__ __forceinline__ void mma16816(float* d, const uint32_t* a,
                                                uint32_t b0, uint32_t b1) {
    asm volatile(
        "mma.sync.aligned.m16n8k16.row.col.f32.f16.f16.f32 "
        "{%0,%1,%2,%3}, {%4,%5,%6,%7}, {%8,%9}, {%0,%1,%2,%3};"
        : "+f"(d[0]), "+f"(d[1]), "+f"(d[2]), "+f"(d[3])
        : "r"(a[0]), "r"(a[1]), "r"(a[2]), "r"(a[3]), "r"(b0), "r"(b1));
}
static __device__ __forceinline__ void mma16808(float* d, uint32_t a0, uint32_t a1,
                                                uint32_t b0) {
    asm volatile(
        "mma.sync.aligned.m16n8k8.row.col.f32.f16.f16.f32 "
        "{%0,%1,%2,%3}, {%4,%5}, {%6}, {%0,%1,%2,%3};"
        : "+f"(d[0]), "+f"(d[1]), "+f"(d[2]), "+f"(d[3])
        : "r"(a0), "r"(a1), "r"(b0));
}
static __device__ __forceinline__ uint32_t pack_hf(float hi, float lo) {
    uint32_t r; asm("cvt.rn.f16x2.f32 %0, %1, %2;" : "=r"(r) : "f"(hi), "f"(lo));
    return r;
}
static __device__ __forceinline__ uint32_t ex2h2(uint32_t a) {
    uint32_t r; asm("ex2.approx.f16x2 %0, %1;" : "=r"(r) : "r"(a));
    return r;
}
static __device__ __forceinline__ uint32_t h2bits(__half2 h) {
    uint32_t r; asm("mov.b32 %0, %1;" : "=r"(r) : "r"(*(uint32_t*)&h));
    return r;
}

#define SW(o) ((uint32_t)(o) ^ ((((uint32_t)(o)) >> 3) & 0x70u))

// smem layout (bytes)
#define OFF_X   0       // 32K  x main tile (256 rows)
#define OFF_XA  32768   // 4K   x aux tile
#define OFF_T   36864   // 2 x 16K t main
#define OFF_TA  69632   // 2 x 2K  t aux
#define OFF_Y   73728   // 2 x 4K  Y (fp16)
#define SMEM_SZ 81920

// =====================================================================
// Merged precompute, MLP=4 loads + 16B stores: 4 threads/row, float4 pairs
// =====================================================================
#define NB_T ((NPAD * 4) / 256)          // 782
#define NB_X ((BTOT * 4) / 256)          // 32
#define NB_Y ((NPAD + 255) / 256)        // 196

__global__ void k_pre(const float* __restrict__ trx, const float* __restrict__ x,
                      const float* __restrict__ trY) {
    __shared__ __half shi[16][256];
    int bx = blockIdx.x;
    int t = threadIdx.x;
    if (bx < NB_T + NB_X) {
        const bool isx = (bx >= NB_T);
        int gid = (isx ? (bx - NB_T) : bx) * 256 + t;
        int row = gid >> 2, q = gid & 3;
        const float* src = isx ? (x + (size_t)row * 64) : (trx + (size_t)row * 64);
        const bool valid = isx || (row < NTRAIN);
        // 4 independent float4 loads (MLP = 4), paired for contiguous stores:
        // chunks {2q, 2q+1} -> halves [8q..8q+7], {2q+8, 2q+9} -> [8q+32..8q+39]
        float4 v[4];
#pragma unroll
        for (int i = 0; i < 4; i++) v[i] = make_float4(0.f, 0.f, 0.f, 0.f);
        if (valid) {
            v[0] = *(const float4*)(src + q * 8);
            v[1] = *(const float4*)(src + q * 8 + 4);
            v[2] = *(const float4*)(src + q * 8 + 32);
            v[3] = *(const float4*)(src + q * 8 + 36);
        }
        float ss = 0.f;
#pragma unroll
        for (int i = 0; i < 4; i++)
            ss += v[i].x * v[i].x + v[i].y * v[i].y + v[i].z * v[i].z + v[i].w * v[i].w;
        const float sc = isx ? K1f : 1.f;
        __half* dstm = (isx ? g_xh : g_txb) + (size_t)row * 64;
        uint4 s0, s1;
        s0.x = h2bits(__floats2half2_rn(v[0].x * sc, v[0].y * sc));
        s0.y = h2bits(__floats2half2_rn(v[0].z * sc, v[0].w * sc));
        s0.z = h2bits(__floats2half2_rn(v[1].x * sc, v[1].y * sc));
        s0.w = h2bits(__floats2half2_rn(v[1].z * sc, v[1].w * sc));
        s1.x = h2bits(__floats2half2_rn(v[2].x * sc, v[2].y * sc));
        s1.y = h2bits(__floats2half2_rn(v[2].z * sc, v[2].w * sc));
        s1.z = h2bits(__floats2half2_rn(v[3].x * sc, v[3].y * sc));
        s1.w = h2bits(__floats2half2_rn(v[3].z * sc, v[3].w * sc));
        *(uint4*)(dstm + q * 8) = s0;
        *(uint4*)(dstm + q * 8 + 32) = s1;
        // norm reduce across the 4 lanes of this row
        ss += __shfl_xor_sync(0xffffffffu, ss, 1, 4);
        ss += __shfl_xor_sync(0xffffffffu, ss, 2, 4);
        if (q == 0) {
            if (isx) {
                float xq = ss * K2f;
                __half hi = __float2half_rn(xq);
                __half lo = __float2half_rn(xq - __half2float(hi));
                __half2* dst = (__half2*)(g_xaux + (size_t)row * 8);
                dst[0] = __halves2half2(hi, lo);
                dst[1] = __floats2half2_rn(1.f, 1.f);
                dst[2] = __floats2half2_rn(0.f, 0.f);
                dst[3] = __floats2half2_rn(0.f, 0.f);
            } else {
                __half hi, lo;
                if (valid) {
                    float tq = ss * K2f;
                    hi = __float2half_rn(tq);
                    lo = __float2half_rn(tq - __half2float(hi));
                } else {
                    hi = __float2half_rn(-60000.f);  // pad rows -> weight 0
                    lo = __float2half_rn(0.f);
                }
                __half2* dst = (__half2*)(g_taux + (size_t)row * 8);
                dst[0] = __floats2half2_rn(1.f, 1.f);
                dst[1] = __halves2half2(hi, lo);
                dst[2] = __floats2half2_rn(0.f, 0.f);
                dst[3] = __floats2half2_rn(0.f, 0.f);
            }
        }
    } else {
        int n0 = (bx - NB_T - NB_X) * 256;
#pragma unroll
        for (int it = 0; it < 16; it++) {
            int e = t + it * 256;
            int r = e >> 4, c = e & 15;
            int row = n0 + r;
            float v = (row < NTRAIN) ? trY[(size_t)row * 16 + c] : 0.f;
            shi[c][r] = __float2half_rn(v);
        }
        __syncthreads();
        if (n0 + t < NPAD) {
#pragma unroll
            for (int c = 0; c < 16; c++)
                g_tyhi[(size_t)c * NPAD + n0 + t] = shi[c][t];
        }
    }
}

// =====================================================================
// Main: MT=256, each warp owns TWO m16 tiles -> B fragments reused 2x
// =====================================================================
__global__ void __launch_bounds__(256, 1) k_main() {
    extern __shared__ char smem[];
    const uint32_t sb = s2u(smem);
    const int t = threadIdx.x;
    const int wid = t >> 5, lane = t & 31;
    const int mbase = blockIdx.x * MT;
    const int s = blockIdx.y;

    // ldmatrix lane mapping
    const int l8 = lane & 7, lq = lane >> 3;
    const int lr = l8 + ((lq & 1) << 3);  // row within 16
    const int lh = lq >> 1;               // 16B column half

    // ones B-fragment for the weight-sum column (n=0 all-ones, others 0)
    const uint32_t bones = (lane < 4) ? 0x3C003C00u : 0u;

    // ---- prologue: x main (256 rows) + x aux ----
#pragma unroll
    for (int i = 0; i < 8; i++) {
        int e = t + i * 256;
        int row = e >> 3, u = e & 7;
        cpa16(sb + OFF_X + SW(row * 128 + u * 16),
              g_xh + (size_t)(mbase + row) * 64 + u * 8);
    }
    cpa16(sb + OFF_XA + t * 16, g_xaux + (size_t)(mbase + t) * 8);

    auto load_chunk = [&](int ch, int b) {
        int nb = ch * BN;
#pragma unroll
        for (int i = 0; i < 4; i++) {
            int e = t + i * 256;
            int row = e >> 3, u = e & 7;
            cpa16(sb + OFF_T + b * 16384 + SW(row * 128 + u * 16),
                  g_txb + (size_t)(nb + row) * 64 + u * 8);
        }
        if (t < 128)
            cpa16(sb + OFF_TA + b * 2048 + t * 16, g_taux + (size_t)(nb + t) * 8);
        {
            int nblk = t >> 4, c = t & 15;
            cpa16(sb + OFF_Y + b * 4096 + c * 256 + (((uint32_t)(nblk ^ c)) << 4),
                  g_tyhi + (size_t)c * NPAD + nb + nblk * 8);
        }
    };
    load_chunk(s, 0);
    cpcommit();
    cpwait0();
    __syncthreads();

    // ---- hoist A fragments: 2 m-tiles x 4 k16, + aux via one ldsm4 ----
    uint32_t ax[2][4][4], axa[4];
#pragma unroll
    for (int mm = 0; mm < 2; mm++)
#pragma unroll
        for (int kt = 0; kt < 4; kt++) {
            uint32_t o = SW((wid * 32 + mm * 16 + lr) * 128 + kt * 32 + lh * 16);
            ldsm4(ax[mm][kt], sb + OFF_X + o);
        }
    ldsm4(axa, sb + OFF_XA + ((wid * 32 + lane) << 4));

    float acc0[2][4], acc1[2][4], acc2[2][4];
#pragma unroll
    for (int mm = 0; mm < 2; mm++)
#pragma unroll
        for (int q = 0; q < 4; q++) { acc0[mm][q] = 0.f; acc1[mm][q] = 0.f; acc2[mm][q] = 0.f; }

    for (int ch = s, jj = 0; ch < NCH; ch += NSPLIT, jj++) {
        const int b = jj & 1;
        if (ch + NSPLIT < NCH) load_chunk(ch + NSPLIT, b ^ 1);
        cpcommit();

        const uint32_t tb = sb + OFF_T + b * 16384;
        const uint32_t tab = sb + OFF_TA + b * 2048;
        const uint32_t yb = sb + OFF_Y + b * 4096;

#pragma unroll
        for (int np = 0; np < 8; np++) {
            // ---- GEMM1 (augmented): c = log2-weight, 2 m-tiles share B ----
            float c[2][2][4];
#pragma unroll
            for (int mm = 0; mm < 2; mm++)
#pragma unroll
                for (int jn = 0; jn < 2; jn++)
#pragma unroll
                    for (int q = 0; q < 4; q++) c[mm][jn][q] = 0.f;
#pragma unroll
            for (int kt = 0; kt < 4; kt++) {
                uint32_t bt[4];
                ldsm4(bt, tb + SW((np * 16 + lr) * 128 + kt * 32 + lh * 16));
#pragma unroll
                for (int mm = 0; mm < 2; mm++) {
                    mma16816(c[mm][0], ax[mm][kt], bt[0], bt[2]);
                    mma16816(c[mm][1], ax[mm][kt], bt[1], bt[3]);
                }
            }
            {
                uint32_t bta[2];
                ldsm2(bta, tab + ((np * 16 + (lane & 15)) << 4));
#pragma unroll
                for (int mm = 0; mm < 2; mm++) {
                    mma16808(c[mm][0], axa[mm * 2], axa[mm * 2 + 1], bta[0]);
                    mma16808(c[mm][1], axa[mm * 2], axa[mm * 2 + 1], bta[1]);
                }
            }
            // ---- epilogue + GEMM2 + weight sum, B (Y) shared across m ----
            uint32_t bh[4];
            {
                uint32_t col = (uint32_t)((2 * np + lh) ^ lr) << 4;
                ldsm4(bh, yb + lr * 256 + col);
            }
#pragma unroll
            for (int mm = 0; mm < 2; mm++) {
                uint32_t ah[4];
#pragma unroll
                for (int jn = 0; jn < 2; jn++) {
                    ah[jn * 2 + 0] = ex2h2(pack_hf(c[mm][jn][1], c[mm][jn][0]));
                    ah[jn * 2 + 1] = ex2h2(pack_hf(c[mm][jn][3], c[mm][jn][2]));
                }
                mma16816(acc0[mm], ah, bh[0], bh[2]);
                mma16816(acc1[mm], ah, bh[1], bh[3]);
                mma16816(acc2[mm], ah, bones, bones);
            }
        }

        cpwait0();
        __syncthreads();
    }

    // ---- store pred partials + weight sums ----
    const int cc = 2 * (lane & 3);
#pragma unroll
    for (int mm = 0; mm < 2; mm++) {
        int rr = mbase + wid * 32 + mm * 16 + (lane >> 2);
        float* p0 = g_pp + ((size_t)s * BTOT + rr) * CDIM;
        float* p1 = p0 + 8 * CDIM;
        *(float2*)(p0 + cc) = make_float2(acc0[mm][0], acc0[mm][1]);
        *(float2*)(p0 + 8 + cc) = make_float2(acc1[mm][0], acc1[mm][1]);
        *(float2*)(p1 + cc) = make_float2(acc0[mm][2], acc0[mm][3]);
        *(float2*)(p1 + 8 + cc) = make_float2(acc1[mm][2], acc1[mm][3]);
        if ((lane & 3) == 0) {
            g_ws[s * BTOT + rr] = acc2[mm][0];
            g_ws[s * BTOT + rr + 8] = acc2[mm][2];
        }
    }
}

// =====================================================================
// Reduce N-split partials + normalize
// =====================================================================
__global__ void k_fin(float* __restrict__ out) {
    int i = blockIdx.x * blockDim.x + threadIdx.x;
    if (i >= BTOT * CDIM) return;
    int qd = i >> 4;
    float acc = 0.f, wsum = 0.f;
#pragma unroll
    for (int s = 0; s < NSPLIT; s++) {
        acc += g_pp[(size_t)s * BTOT * CDIM + i];
        wsum += g_ws[s * BTOT + qd];
    }
    out[i] = acc / (wsum + 1e-10f);
}

extern "C" void kernel_launch(void* const* d_in, const int* in_sizes, int n_in,
                              void* d_out, int out_size) {
    const float* x   = (const float*)d_in[0];
    const float* trx = (const float*)d_in[1];
    const float* trY = (const float*)d_in[2];
    float* out = (float*)d_out;

    cudaFuncSetAttribute(k_main, cudaFuncAttributeMaxDynamicSharedMemorySize, SMEM_SZ);

    k_pre<<<NB_T + NB_X + NB_Y, 256>>>(trx, x, trY);
    dim3 grid(BTOT / MT, NSPLIT);
    k_main<<<grid, 256, SMEM_SZ>>>();
    k_fin<<<(BTOT * CDIM + 255) / 256, 256>>>(out);
}